// round 15
// baseline (speedup 1.0000x reference)
#include <cuda_runtime.h>
#include <cuda_bf16.h>
#include <math.h>
#include <stdint.h>

#define NNODES 50000
#define NPADM  50048
#define NMCH   391
#define NEDGES 200000
#define TOTE   (NEDGES + NNODES)
#define EMB    300
#define EMB4   75
#define NKT    19
#define DK     256
#define BGR    1000
#define NPER   50
#define NLAYERS 5
#define PADF   16
#define NJB    3
#define NTL    14

// ---------------- scratch (device globals) ----------------
__device__ float g_h[NNODES * EMB];
__device__ float g_hW[NNODES * EMB];
__device__ uint4 g_hfa_hi[NMCH * NKT * 8 * 32];
__device__ uint4 g_hfa_lo[NMCH * NKT * 8 * 32];
__device__ uint4 g_wfb[NLAYERS * NJB * NKT * NTL * 32];
__device__ float g_mf[BGR * EMB];
__device__ float g_ve_all[NLAYERS * 2 * EMB];
__device__ float g_qk[BGR * EMB];
__device__ float g_wsum[BGR * EMB];
__device__ float g_mean[BGR * EMB];
__device__ float g_wqt[EMB * DK];
__device__ float g_wvt[EMB * DK];
__device__ float g_mlt[EMB * DK];
__device__ float g_lgt[EMB * DK];
__device__ float g_ph1t[DK * 512];
// CSR
__device__ int g_deg[NNODES];
__device__ int g_off[NNODES + 1];
__device__ int g_cur[NNODES];
__device__ int g_csr_src[TOTE];
__device__ float2 g_csr_ea[TOTE];

// ---------------- helpers ----------------
__device__ __forceinline__ void split_pack(float v0, float v1, uint32_t& hi, uint32_t& lo)
{
    __nv_bfloat16 h0 = __float2bfloat16(v0);
    __nv_bfloat16 h1 = __float2bfloat16(v1);
    __nv_bfloat16 l0 = __float2bfloat16(v0 - __bfloat162float(h0));
    __nv_bfloat16 l1 = __float2bfloat16(v1 - __bfloat162float(h1));
    __nv_bfloat162 H = __halves2bfloat162(h0, h1);
    __nv_bfloat162 L = __halves2bfloat162(l0, l1);
    hi = *(uint32_t*)&H;
    lo = *(uint32_t*)&L;
}

__device__ __forceinline__ uint32_t smem_u32(const void* p) {
    uint32_t a;
    asm("{ .reg .u64 t; cvta.to.shared.u64 t, %1; cvt.u32.u64 %0, t; }" : "=r"(a) : "l"(p));
    return a;
}

#define MMA_BF16(d, a, b) asm volatile( \
    "mma.sync.aligned.m16n8k16.row.col.f32.bf16.bf16.f32 " \
    "{%0,%1,%2,%3},{%4,%5,%6,%7},{%8,%9},{%0,%1,%2,%3};\n" \
    : "+f"(d[0]), "+f"(d[1]), "+f"(d[2]), "+f"(d[3]) \
    : "r"((a)[0]), "r"((a)[1]), "r"((a)[2]), "r"((a)[3]), "r"((b)[0]), "r"((b)[1]))

#define LDS128(r, a) asm volatile( \
    "ld.shared.v4.b32 {%0,%1,%2,%3}, [%4];" \
    : "=r"((r)[0]), "=r"((r)[1]), "=r"((r)[2]), "=r"((r)[3]) : "r"(a))

#define MB_INIT(m) asm volatile("mbarrier.init.shared.b64 [%0], %1;" \
    :: "r"(m), "r"(1u) : "memory")
#define MB_EXPECT(m, n) asm volatile("mbarrier.arrive.expect_tx.shared.b64 _, [%0], %1;" \
    :: "r"(m), "r"((uint32_t)(n)) : "memory")
#define BULK_G2S(dst, src, sz, m) asm volatile( \
    "cp.async.bulk.shared::cluster.global.mbarrier::complete_tx::bytes [%0], [%1], %2, [%3];" \
    :: "r"(dst), "l"(src), "r"((uint32_t)(sz)), "r"(m) : "memory")

__device__ __forceinline__ void mbar_wait(uint32_t addr, uint32_t parity)
{
    uint32_t done;
    do {
        asm volatile(
            "{\n\t.reg .pred p;\n\t"
            "mbarrier.try_wait.parity.acquire.cta.shared::cta.b64 p, [%1], %2, 0x989680;\n\t"
            "selp.b32 %0,1,0,p;\n\t}"
            : "=r"(done) : "r"(addr), "r"(parity) : "memory");
    } while (!done);
}

#define HSW 332
__device__ __forceinline__ void write_frags_from_smem(float (*hs)[HSW], int mtile,
                                                      int warp, int lane)
{
    int gid = lane >> 2, tig = lane & 3;
    int mc = mtile >> 3, mt8 = mtile & 7;
    for (int kt = warp; kt < NKT; kt += 8) {
        int kb = kt * 16;
        float v00 = hs[gid][kb + 2 * tig],     v01 = hs[gid][kb + 2 * tig + 1];
        float v10 = hs[gid + 8][kb + 2 * tig], v11 = hs[gid + 8][kb + 2 * tig + 1];
        float v20 = hs[gid][kb + 8 + 2 * tig],     v21 = hs[gid][kb + 8 + 2 * tig + 1];
        float v30 = hs[gid + 8][kb + 8 + 2 * tig], v31 = hs[gid + 8][kb + 8 + 2 * tig + 1];
        uint4 Hi, Lo;
        split_pack(v00, v01, Hi.x, Lo.x);
        split_pack(v10, v11, Hi.y, Lo.y);
        split_pack(v20, v21, Hi.z, Lo.z);
        split_pack(v30, v31, Hi.w, Lo.w);
        size_t idx = (((size_t)mc * NKT + kt) * 8 + mt8) * 32 + lane;
        g_hfa_hi[idx] = Hi;
        g_hfa_lo[idx] = Lo;
    }
}

// ---------------- node init -> A fragments ----------------
__global__ void __launch_bounds__(256) k_init_frag(const int* __restrict__ x_type,
                                                   const float* __restrict__ x_feat,
                                                   const float* __restrict__ x_emb,
                                                   const float* __restrict__ x_weight)
{
    __shared__ float hs[16][HSW];
    int tid = threadIdx.x, warp = tid >> 5, lane = tid & 31;
    int base = blockIdx.x * 16;
#pragma unroll
    for (int i = 0; i < 2; i++) {
        int row = warp * 2 + i;
        int n = base + row;
        int t = __ldg(x_type + n);
#pragma unroll
        for (int ch = 0; ch < 3; ch++) {
            int c = lane + 32 * ch;
            if (c < EMB4) {
                float4 acc = __ldg((const float4*)(x_emb + (size_t)t * EMB) + c);
#pragma unroll
                for (int k = 0; k < PADF; k++) {
                    float f = __ldg(x_feat + (size_t)n * PADF + k);
                    float4 w = __ldg((const float4*)(x_weight + (size_t)k * EMB) + c);
                    acc.x = fmaf(f, w.x, acc.x); acc.y = fmaf(f, w.y, acc.y);
                    acc.z = fmaf(f, w.z, acc.z); acc.w = fmaf(f, w.w, acc.w);
                }
                *(float4*)&hs[row][4 * c] = acc;
            }
        }
        hs[row][300 + lane] = 0.f;
    }
    __syncthreads();
    write_frags_from_smem(hs, blockIdx.x, warp, lane);
}

// zero fragments for pad rows 50000..50047 (mc=390, mt8=5..7)
__global__ void k_zero_padfrag()
{
    int idx = blockIdx.x * blockDim.x + threadIdx.x;
    if (idx >= NKT * 3 * 32) return;
    int lane = idx & 31, mt8 = 5 + ((idx >> 5) % 3), kt = (idx >> 5) / 3;
    size_t o = (((size_t)390 * NKT + kt) * 8 + mt8) * 32 + lane;
    uint4 z = make_uint4(0, 0, 0, 0);
    g_hfa_hi[o] = z;
    g_hfa_lo[o] = z;
}

// ---------------- weight split -> B fragments ----------------
__global__ void k_wsplit_frag(const float* __restrict__ mlp_w)
{
    int idx = blockIdx.x * blockDim.x + threadIdx.x;
    if (idx >= NLAYERS * NJB * NKT * NTL * 32) return;
    int lane = idx & 31;
    int ntl = (idx >> 5) % NTL;
    int kt = (idx >> 5) / NTL % NKT;
    int jblk = (idx >> 5) / (NTL * NKT) % NJB;
    int l = idx / (32 * NTL * NKT * NJB);
    int gid = lane >> 2, tig = lane & 3;
    int j = jblk * 112 + ntl * 8 + gid;
    int k0 = kt * 16 + 2 * tig;
    int k1 = k0 + 8;
    const float* W = mlp_w + (size_t)l * EMB * EMB + (size_t)j * EMB;
    float w00 = (j < EMB && k0 < EMB) ? __ldg(W + k0) : 0.f;
    float w01 = (j < EMB && k0 + 1 < EMB) ? __ldg(W + k0 + 1) : 0.f;
    float w10 = (j < EMB && k1 < EMB) ? __ldg(W + k1) : 0.f;
    float w11 = (j < EMB && k1 + 1 < EMB) ? __ldg(W + k1 + 1) : 0.f;
    uint4 o;
    split_pack(w00, w01, o.x, o.z);
    split_pack(w10, w11, o.y, o.w);
    g_wfb[idx] = o;
}

// ---------------- metal feature ----------------
__global__ void k_mf(const int* __restrict__ metal_type, const float* __restrict__ metal_feat,
                     const float* __restrict__ me1_w, const float* __restrict__ me1_b,
                     const float* __restrict__ me2)
{
    int idx = blockIdx.x * blockDim.x + threadIdx.x;
    if (idx >= BGR * EMB) return;
    int b = idx / EMB, j = idx % EMB;
    float acc = __ldg(me1_b + j) + __ldg(me2 + (size_t)__ldg(metal_type + b) * EMB + j);
#pragma unroll
    for (int k = 0; k < 17; k++)
        acc = fmaf(__ldg(metal_feat + (size_t)b * 17 + k), __ldg(me1_w + (size_t)j * 17 + k), acc);
    g_mf[idx] = acc;
}

// ---------------- transpose readout weights ----------------
__global__ void k_transpose_all(const float* __restrict__ wq, const float* __restrict__ wv,
                                const float* __restrict__ ml, const float* __restrict__ lg,
                                const float* __restrict__ ph1)
{
    int idx = blockIdx.x * blockDim.x + threadIdx.x;
    const int SZ1 = DK * EMB;
    if (idx < 4 * SZ1) {
        int w = idx / SZ1, i = idx % SZ1;
        int d = i / EMB, j = i % EMB;
        float v = (w == 0) ? wq[i] : (w == 1) ? wv[i] : (w == 2) ? ml[i] : lg[i];
        float* dst = (w == 0) ? g_wqt : (w == 1) ? g_wvt : (w == 2) ? g_mlt : g_lgt;
        dst[(size_t)j * DK + d] = v;
    } else {
        int i = idx - 4 * SZ1;
        if (i < 512 * DK) {
            int o = i / DK, d = i % DK;
            g_ph1t[(size_t)d * 512 + o] = ph1[i];
        }
    }
}

// ---------------- all layers' edge vectors ----------------
__global__ void k_ve_all(const float* __restrict__ ew1, const float* __restrict__ mlp_w)
{
    int o = (blockIdx.x * blockDim.x + threadIdx.x) >> 5;
    if (o >= NLAYERS * 2 * EMB) return;
    int lane = threadIdx.x & 31;
    int l = o / (2 * EMB);
    int rem = o % (2 * EMB);
    int w = rem / EMB, col = rem % EMB;
    const float* e = ew1 + (size_t)l * 2 * EMB + (size_t)w * EMB;
    const float* wr = mlp_w + (size_t)l * EMB * EMB + (size_t)col * EMB;
    float s = 0.f;
    for (int k = lane; k < EMB; k += 32) s = fmaf(__ldg(e + k), __ldg(wr + k), s);
#pragma unroll
    for (int off = 16; off; off >>= 1) s += __shfl_xor_sync(0xffffffffu, s, off);
    if (lane == 0) g_ve_all[o] = s;
}

// ---------------- CSR build ----------------
__global__ void k_deg_init() {
    int i = blockIdx.x * blockDim.x + threadIdx.x;
    if (i < NNODES) g_deg[i] = 1;
}
__global__ void k_deg_count(const int* __restrict__ eidx) {
    int e = blockIdx.x * blockDim.x + threadIdx.x;
    if (e < NEDGES) atomicAdd(&g_deg[__ldg(eidx + NEDGES + e)], 1);
}
__global__ void k_scan() {
    __shared__ int ps[1024];
    const int C = (NNODES + 1023) / 1024;
    int t = threadIdx.x;
    int base = t * C;
    int s = 0;
    for (int i = base; i < base + C && i < NNODES; i++) s += g_deg[i];
    ps[t] = s;
    __syncthreads();
    for (int off = 1; off < 1024; off <<= 1) {
        int v = (t >= off) ? ps[t - off] : 0;
        __syncthreads();
        ps[t] += v;
        __syncthreads();
    }
    int ex = (t == 0) ? 0 : ps[t - 1];
    for (int i = base; i < base + C && i < NNODES; i++) {
        g_off[i] = ex; g_cur[i] = ex;
        ex += g_deg[i];
    }
    if (t == 1023) g_off[NNODES] = TOTE;
}
__global__ void k_fill(const int* __restrict__ eidx, const float* __restrict__ eattr) {
    int idx = blockIdx.x * blockDim.x + threadIdx.x;
    if (idx >= TOTE) return;
    int src, col; float2 ea;
    if (idx < NEDGES) {
        src = __ldg(eidx + idx);
        col = __ldg(eidx + NEDGES + idx);
        ea = __ldg((const float2*)eattr + idx);
    } else {
        src = col = idx - NEDGES;
        ea = make_float2(0.f, 4.f);
    }
    int pos = atomicAdd(&g_cur[col], 1);
    g_csr_src[pos] = src;
    g_csr_ea[pos] = ea;
}

// ---------------- GEMM: one launch (391,3), block-uniform compile-time NTLW -------
#define STG    15360
#define MBOFF  (4 * STG)
#define GEMM_SMEM (MBOFF + 32)

template<int NTLW>
__device__ __forceinline__ void gemm_body(uint32_t sb, int layer, int jblk, int mc,
                                          const float* __restrict__ bias,
                                          int tid, int warp, int lane)
{
    int gid = lane >> 2, tig = lane & 3;
    int wm = warp & 3, wn = warp >> 2;
    int nbase = wn * NTLW;

#define ISSUE(kt_) do { \
    int s_ = (kt_) & 3; \
    uint32_t dst_ = sb + (uint32_t)s_ * STG; \
    uint32_t mb_ = sb + MBOFF + s_ * 8; \
    size_t ao_ = ((size_t)mc * NKT + (kt_)) * 256; \
    size_t bo_ = (((size_t)layer * NJB + jblk) * NKT + (kt_)) * (NTL * 32); \
    MB_EXPECT(mb_, STG); \
    BULK_G2S(dst_, g_hfa_hi + ao_, 4096, mb_); \
    BULK_G2S(dst_ + 4096, g_hfa_lo + ao_, 4096, mb_); \
    BULK_G2S(dst_ + 8192, g_wfb + bo_, 7168, mb_); \
} while (0)

    if (tid == 0) { ISSUE(0); ISSUE(1); ISSUE(2); }

    float acc[2][NTLW][4];
#pragma unroll
    for (int mt = 0; mt < 2; mt++)
#pragma unroll
        for (int nj = 0; nj < NTLW; nj++)
#pragma unroll
            for (int r = 0; r < 4; r++) acc[mt][nj][r] = 0.f;

    for (int kt = 0; kt < NKT; kt++) {
        uint32_t stg = sb + (uint32_t)(kt & 3) * STG;
        mbar_wait(sb + MBOFF + (kt & 3) * 8, (kt >> 2) & 1);

        uint32_t ah[2][4], al[2][4], bq[NTLW][4];
#pragma unroll
        for (int mt = 0; mt < 2; mt++) {
            uint32_t ao = ((uint32_t)(wm * 2 + mt) * 32 + lane) * 16;
            LDS128(ah[mt], stg + ao);
            LDS128(al[mt], stg + 4096 + ao);
        }
#pragma unroll
        for (int nj = 0; nj < NTLW; nj++) {
            uint32_t bo = ((uint32_t)(nbase + nj) * 32 + lane) * 16;
            LDS128(bq[nj], stg + 8192 + bo);
        }
#pragma unroll
        for (int mt = 0; mt < 2; mt++)
#pragma unroll
            for (int nj = 0; nj < NTLW; nj++) MMA_BF16(acc[mt][nj], ah[mt], bq[nj]);
#pragma unroll
        for (int mt = 0; mt < 2; mt++)
#pragma unroll
            for (int nj = 0; nj < NTLW; nj++) MMA_BF16(acc[mt][nj], al[mt], bq[nj]);
#pragma unroll
        for (int mt = 0; mt < 2; mt++)
#pragma unroll
            for (int nj = 0; nj < NTLW; nj++) MMA_BF16(acc[mt][nj], ah[mt], bq[nj] + 2);

        __syncthreads();
        if (tid == 0 && kt + 3 < NKT) ISSUE(kt + 3);
    }
#undef ISSUE

#pragma unroll
    for (int mt = 0; mt < 2; mt++) {
        int m = mc * 128 + (wm * 2 + mt) * 16 + gid;
#pragma unroll
        for (int nj = 0; nj < NTLW; nj++) {
            int j = jblk * 112 + (nbase + nj) * 8 + 2 * tig;
            if (j < EMB) {
                float b0 = __ldg(bias + j), b1 = __ldg(bias + j + 1);
                if (m < NNODES)
                    *(float2*)(g_hW + (size_t)m * EMB + j) =
                        make_float2(acc[mt][nj][0] + b0, acc[mt][nj][1] + b1);
                if (m + 8 < NNODES)
                    *(float2*)(g_hW + (size_t)(m + 8) * EMB + j) =
                        make_float2(acc[mt][nj][2] + b0, acc[mt][nj][3] + b1);
            }
        }
    }
}

__global__ void __launch_bounds__(256, 2) k_gemm_tma(int layer, const float* __restrict__ bias)
{
    extern __shared__ char smem[];
    uint32_t sb = smem_u32(smem);
    int tid = threadIdx.x, warp = tid >> 5, lane = tid & 31;
    int mc = blockIdx.x, jblk = blockIdx.y;

    if (tid == 0) {
#pragma unroll
        for (int s = 0; s < 4; s++) MB_INIT(sb + MBOFF + s * 8);
    }
    __syncthreads();

    if (jblk < 2) gemm_body<7>(sb, layer, jblk, mc, bias, tid, warp, lane);
    else          gemm_body<5>(sb, layer, jblk, mc, bias, tid, warp, lane);
}

// ---- edge-pair accumulate helper (MLP 6) ----
__device__ __forceinline__ void aggr_accum_pair(float4* acc, const float4* e0v, const float4* e1v,
                                                int lane, int src0, float2 ea0,
                                                int src1, float2 ea1)
{
    const float4* r0 = (const float4*)(g_hW + (size_t)src0 * EMB);
    const float4* r1 = (const float4*)(g_hW + (size_t)src1 * EMB);
    float4 x0[3], x1[3];
#pragma unroll
    for (int i = 0; i < 3; i++) {
        int c = lane + 32 * i;
        if (c < EMB4) { x0[i] = r0[c]; x1[i] = r1[c]; }
    }
#pragma unroll
    for (int i = 0; i < 3; i++) {
        int c = lane + 32 * i;
        if (c < EMB4) {
            acc[i].x += fmaxf(fmaf(ea0.y, e1v[i].x, fmaf(ea0.x, e0v[i].x, x0[i].x)), 0.f);
            acc[i].y += fmaxf(fmaf(ea0.y, e1v[i].y, fmaf(ea0.x, e0v[i].y, x0[i].y)), 0.f);
            acc[i].z += fmaxf(fmaf(ea0.y, e1v[i].z, fmaf(ea0.x, e0v[i].z, x0[i].z)), 0.f);
            acc[i].w += fmaxf(fmaf(ea0.y, e1v[i].w, fmaf(ea0.x, e0v[i].w, x0[i].w)), 0.f);
            acc[i].x += fmaxf(fmaf(ea1.y, e1v[i].x, fmaf(ea1.x, e0v[i].x, x1[i].x)), 0.f);
            acc[i].y += fmaxf(fmaf(ea1.y, e1v[i].y, fmaf(ea1.x, e0v[i].y, x1[i].y)), 0.f);
            acc[i].z += fmaxf(fmaf(ea1.y, e1v[i].z, fmaf(ea1.x, e0v[i].z, x1[i].z)), 0.f);
            acc[i].w += fmaxf(fmaf(ea1.y, e1v[i].w, fmaf(ea1.x, e0v[i].w, x1[i].w)), 0.f);
        }
    }
}

__device__ __forceinline__ void aggr_accum_one(float4* acc, const float4* e0v, const float4* e1v,
                                               int lane, int src, float2 ea)
{
    const float4* r = (const float4*)(g_hW + (size_t)src * EMB);
#pragma unroll
    for (int i = 0; i < 3; i++) {
        int c = lane + 32 * i;
        if (c < EMB4) {
            float4 x = r[c];
            acc[i].x += fmaxf(fmaf(ea.y, e1v[i].x, fmaf(ea.x, e0v[i].x, x.x)), 0.f);
            acc[i].y += fmaxf(fmaf(ea.y, e1v[i].y, fmaf(ea.x, e0v[i].y, x.y)), 0.f);
            acc[i].z += fmaxf(fmaf(ea.y, e1v[i].z, fmaf(ea.x, e0v[i].z, x.z)), 0.f);
            acc[i].w += fmaxf(fmaf(ea.y, e1v[i].w, fmaf(ea.x, e0v[i].w, x.w)), 0.f);
        }
    }
}

// ---------------- aggregation + BN + relu -> A fragments (layers 0..3) ----------------
__global__ void __launch_bounds__(256) k_aggr_frag(int layer,
                                                   const float* __restrict__ rm,
                                                   const float* __restrict__ rv,
                                                   const float* __restrict__ gg,
                                                   const float* __restrict__ bb)
{
    __shared__ float hs[16][HSW];
    int tid = threadIdx.x, warp = tid >> 5, lane = tid & 31;
    int base = blockIdx.x * 16;
    const float4* ve4 = (const float4*)(g_ve_all + (size_t)layer * 2 * EMB);

    float4 e0[3], e1[3], bm[3], bv[3], bg[3], bbb[3];
#pragma unroll
    for (int i = 0; i < 3; i++) {
        int c = lane + 32 * i;
        if (c < EMB4) {
            e0[i] = __ldg(ve4 + c); e1[i] = __ldg(ve4 + EMB4 + c);
            bm[i] = __ldg((const float4*)rm + c);
            bv[i] = __ldg((const float4*)rv + c);
            bg[i] = __ldg((const float4*)gg + c);
            bbb[i] = __ldg((const float4*)bb + c);
        }
    }
#pragma unroll
    for (int ni = 0; ni < 2; ni++) {
        int row = warp * 2 + ni;
        int gw = base + row;
        float4 acc[3];
#pragma unroll
        for (int i = 0; i < 3; i++) acc[i] = make_float4(0.f, 0.f, 0.f, 0.f);
        int beg = g_off[gw], end = g_off[gw + 1];
        int e = beg;
        for (; e + 1 < end; e += 2) {
            int s0 = g_csr_src[e], s1 = g_csr_src[e + 1];
            float2 a0 = g_csr_ea[e], a1 = g_csr_ea[e + 1];
            aggr_accum_pair(acc, e0, e1, lane, s0, a0, s1, a1);
        }
        if (e < end) aggr_accum_one(acc, e0, e1, lane, g_csr_src[e], g_csr_ea[e]);

#pragma unroll
        for (int i = 0; i < 3; i++) {
            int c = lane + 32 * i;
            if (c < EMB4) {
                float4 y;
                y.x = fmaxf((acc[i].x - bm[i].x) * rsqrtf(bv[i].x + 1e-5f) * bg[i].x + bbb[i].x, 0.f);
                y.y = fmaxf((acc[i].y - bm[i].y) * rsqrtf(bv[i].y + 1e-5f) * bg[i].y + bbb[i].y, 0.f);
                y.z = fmaxf((acc[i].z - bm[i].z) * rsqrtf(bv[i].z + 1e-5f) * bg[i].z + bbb[i].z, 0.f);
                y.w = fmaxf((acc[i].w - bm[i].w) * rsqrtf(bv[i].w + 1e-5f) * bg[i].w + bbb[i].w, 0.f);
                *(float4*)&hs[row][4 * c] = y;
            }
        }
        hs[row][300 + lane] = 0.f;
    }
    __syncthreads();
    write_frags_from_smem(hs, blockIdx.x, warp, lane);
}

// ---------------- last layer aggregation + BN (no relu) -> g_h linear ----------------
__global__ void __launch_bounds__(256) k_aggr_last(int layer,
                                                   const float* __restrict__ rm,
                                                   const float* __restrict__ rv,
                                                   const float* __restrict__ gg,
                                                   const float* __restrict__ bb)
{
    int gw = (blockIdx.x * blockDim.x + threadIdx.x) >> 5;
    if (gw >= NNODES) return;
    int lane = threadIdx.x & 31;
    const float4* ve4 = (const float4*)(g_ve_all + (size_t)layer * 2 * EMB);

    float4 acc[3], e0[3], e1[3];
#pragma unroll
    for (int i = 0; i < 3; i++) {
        acc[i] = make_float4(0.f, 0.f, 0.f, 0.f);
        int c = lane + 32 * i;
        if (c < EMB4) { e0[i] = __ldg(ve4 + c); e1[i] = __ldg(ve4 + EMB4 + c); }
    }
    int beg = g_off[gw], end = g_off[gw + 1];
    int e = beg;
    for (; e + 1 < end; e += 2) {
        int s0 = g_csr_src[e], s1 = g_csr_src[e + 1];
        float2 a0 = g_csr_ea[e], a1 = g_csr_ea[e + 1];
        aggr_accum_pair(acc, e0, e1, lane, s0, a0, s1, a1);
    }
    if (e < end) aggr_accum_one(acc, e0, e1, lane, g_csr_src[e], g_csr_ea[e]);

#pragma unroll
    for (int i = 0; i < 3; i++) {
        int c = lane + 32 * i;
        if (c < EMB4) {
            float4 m = __ldg((const float4*)rm + c);
            float4 v = __ldg((const float4*)rv + c);
            float4 g4 = __ldg((const float4*)gg + c);
            float4 b4 = __ldg((const float4*)bb + c);
            float4 y;
            y.x = (acc[i].x - m.x) * rsqrtf(v.x + 1e-5f) * g4.x + b4.x;
            y.y = (acc[i].y - m.y) * rsqrtf(v.y + 1e-5f) * g4.y + b4.y;
            y.z = (acc[i].z - m.z) * rsqrtf(v.z + 1e-5f) * g4.z + b4.z;
            y.w = (acc[i].w - m.w) * rsqrtf(v.w + 1e-5f) * g4.w + b4.w;
            ((float4*)(g_h + (size_t)gw * EMB))[c] = y;
        }
    }
}

// ---------------- readout: fused Q + qk  (qk[b,i] = sum_d (mf[b]@wq.T)[d] * wk[d,i]) ----
__global__ void k_qqk(const float* __restrict__ wk)
{
    __shared__ float mfs[4][EMB];
    __shared__ float Qs[4][DK];
    int b0 = blockIdx.x * 4, tid = threadIdx.x;
    for (int i = tid; i < 4 * EMB; i += 256)
        mfs[i / EMB][i % EMB] = g_mf[(size_t)(b0 + i / EMB) * EMB + i % EMB];
    __syncthreads();
    {
        float acc[4] = {0.f, 0.f, 0.f, 0.f};
        for (int j = 0; j < EMB; j++) {
            float w = g_wqt[(size_t)j * DK + tid];
#pragma unroll
            for (int g = 0; g < 4; g++) acc[g] = fmaf(mfs[g][j], w, acc[g]);
        }
#pragma unroll
        for (int g = 0; g < 4; g++) Qs[g][tid] = acc[g];
    }
    __syncthreads();
#pragma unroll
    for (int rep = 0; rep < 2; rep++) {
        int j = tid + rep * 256;
        if (j < EMB) {
            float acc[4] = {0.f, 0.f, 0.f, 0.f};
            for (int d = 0; d < DK; d++) {
                float w = __ldg(wk + (size_t)d * EMB + j);
#pragma unroll
                for (int g = 0; g < 4; g++) acc[g] = fmaf(Qs[g][d], w, acc[g]);
            }
#pragma unroll
            for (int g = 0; g < 4; g++) g_qk[(size_t)(b0 + g) * EMB + j] = acc[g];
        }
    }
}

__global__ void k_attn()
{
    __shared__ float qks[EMB];
    __shared__ float sc[NPER];
    __shared__ float p[NPER];
    int b = blockIdx.x, tid = threadIdx.x;
    for (int i = tid; i < EMB; i += 256) qks[i] = g_qk[(size_t)b * EMB + i];
    __syncthreads();
    int warp = tid >> 5, lane = tid & 31;
    const float* hb = g_h + (size_t)b * NPER * EMB;
    for (int k = warp; k < NPER; k += 8) {
        float s = 0.f;
        for (int i = lane; i < EMB; i += 32) s = fmaf(qks[i], hb[(size_t)k * EMB + i], s);
#pragma unroll
        for (int off = 16; off; off >>= 1) s += __shfl_xor_sync(0xffffffffu, s, off);
        if (lane == 0) sc[k] = s * (1.0f / 16.0f);
    }
    __syncthreads();
    if (tid == 0) {
        float mx = -1e30f;
        for (int k = 0; k < NPER; k++) mx = fmaxf(mx, sc[k]);
        float ssum = 0.f;
        for (int k = 0; k < NPER; k++) { float e = expf(sc[k] - mx); p[k] = e; ssum += e; }
        float inv = 1.f / ssum;
        for (int k = 0; k < NPER; k++) p[k] *= inv;
    }
    __syncthreads();
    for (int j = tid; j < EMB; j += 256) {
        float ws = 0.f, mn = 0.f;
        for (int k = 0; k < NPER; k++) {
            float v = hb[(size_t)k * EMB + j];
            ws = fmaf(p[k], v, ws); mn += v;
        }
        g_wsum[(size_t)b * EMB + j] = ws;
        g_mean[(size_t)b * EMB + j] = mn * (1.0f / NPER);
    }
}

__global__ void k_final(const float* __restrict__ ml_b, const float* __restrict__ lg_b,
                        const float* __restrict__ ph1_b, const float* __restrict__ ph2_w,
                        const float* __restrict__ ph2_b, float* __restrict__ out)
{
    __shared__ float ws[4][EMB], mfs[4][EMB], mns[4][EMB];
    __shared__ float feat[4][DK];
    __shared__ float red[256];
    int b0 = blockIdx.x * 4, tid = threadIdx.x;
    for (int i = tid; i < 4 * EMB; i += 256) {
        int g = i / EMB, j = i % EMB;
        ws[g][j]  = g_wsum[(size_t)(b0 + g) * EMB + j];
        mfs[g][j] = g_mf[(size_t)(b0 + g) * EMB + j];
        mns[g][j] = g_mean[(size_t)(b0 + g) * EMB + j];
    }
    __syncthreads();
    int d = tid;
    float a[4], m2[4], lg[4];
    float mb = __ldg(ml_b + d), lb = __ldg(lg_b + d);
#pragma unroll
    for (int g = 0; g < 4; g++) { a[g] = 0.f; m2[g] = mb; lg[g] = lb; }
    for (int k = 0; k < EMB; k++) {
        float wv_ = g_wvt[(size_t)k * DK + d];
        float ml_ = g_mlt[(size_t)k * DK + d];
        float lg_ = g_lgt[(size_t)k * DK + d];
#pragma unroll
        for (int g = 0; g < 4; g++) {
            a[g]  = fmaf(wv_, ws[g][k],  a[g]);
            m2[g] = fmaf(ml_, mfs[g][k], m2[g]);
            lg[g] = fmaf(lg_, mns[g][k], lg[g]);
        }
    }
#pragma unroll
    for (int g = 0; g < 4; g++)
        feat[g][d] = fmaxf(a[g], 0.f) + fmaxf(m2[g], 0.f) + fmaxf(lg[g], 0.f);
    __syncthreads();
    float part[4] = {0.f, 0.f, 0.f, 0.f};
#pragma unroll
    for (int rep = 0; rep < 2; rep++) {
        int o = tid + rep * 256;
        float t[4];
        float pb = __ldg(ph1_b + o);
#pragma unroll
        for (int g = 0; g < 4; g++) t[g] = pb;
        for (int k = 0; k < DK; k++) {
            float w = g_ph1t[(size_t)k * 512 + o];
#pragma unroll
            for (int g = 0; g < 4; g++) t[g] = fmaf(w, feat[g][k], t[g]);
        }
        float p2 = __ldg(ph2_w + o);
#pragma unroll
        for (int g = 0; g < 4; g++) {
            float x = t[g];
            float sp = (x > 20.f) ? x : log1pf(expf(x));
            part[g] = fmaf(sp, p2, part[g]);
        }
    }
    for (int g = 0; g < 4; g++) {
        red[tid] = part[g];
        __syncthreads();
        for (int s = 128; s; s >>= 1) {
            if (tid < s) red[tid] += red[tid + s];
            __syncthreads();
        }
        if (tid == 0) out[b0 + g] = red[0] + __ldg(ph2_b);
        __syncthreads();
    }
}

// ---------------- launch ----------------
extern "C" void kernel_launch(void* const* d_in, const int* in_sizes, int n_in,
                              void* d_out, int out_size)
{
    const int*   x_type     = (const int*)d_in[0];
    const float* x_feat     = (const float*)d_in[1];
    const int*   edge_index = (const int*)d_in[2];
    const float* edge_attr  = (const float*)d_in[3];
    const int*   metal_type = (const int*)d_in[4];
    const float* metal_feat = (const float*)d_in[5];
    const float* x_emb      = (const float*)d_in[6];
    const float* x_weight   = (const float*)d_in[7];
    const float* ew1        = (const float*)d_in[8];
    const float* mlp_w      = (const float*)d_in[9];
    const float* mlp_b      = (const float*)d_in[10];
    const float* bn_g       = (const float*)d_in[11];
    const float* bn_b       = (const float*)d_in[12];
    const float* bn_rm      = (const float*)d_in[13];
    const float* bn_rv      = (const float*)d_in[14];
    const float* me1_w      = (const float*)d_in[15];
    const float* me1_b      = (const float*)d_in[16];
    const float* me2        = (const float*)d_in[17];
    const float* wq         = (const float*)d_in[18];
    const float* wk         = (const float*)d_in[19];
    const float* wv         = (const float*)d_in[20];
    const float* ml_w       = (const float*)d_in[21];
    const float* ml_b       = (const float*)d_in[22];
    const float* lg_w       = (const float*)d_in[23];
    const float* lg_b       = (const float*)d_in[24];
    const float* ph1_w      = (const float*)d_in[25];
    const float* ph1_b      = (const float*)d_in[26];
    const float* ph2_w      = (const float*)d_in[27];
    const float* ph2_b      = (const float*)d_in[28];
    float* out = (float*)d_out;

    cudaFuncSetAttribute(k_gemm_tma, cudaFuncAttributeMaxDynamicSharedMemorySize, GEMM_SMEM);

    k_init_frag<<<NNODES / 16, 256>>>(x_type, x_feat, x_emb, x_weight);
    k_zero_padfrag<<<(NKT * 3 * 32 + 255) / 256, 256>>>();
    k_wsplit_frag<<<(NLAYERS * NJB * NKT * NTL * 32 + 255) / 256, 256>>>(mlp_w);
    k_mf<<<(BGR * EMB + 255) / 256, 256>>>(metal_type, metal_feat, me1_w, me1_b, me2);
    k_transpose_all<<<(4 * DK * EMB + 512 * DK + 255) / 256, 256>>>(wq, wv, ml_w, lg_w, ph1_w);
    k_ve_all<<<(NLAYERS * 2 * EMB * 32 + 255) / 256, 256>>>(ew1, mlp_w);

    // CSR build (once per launch)
    k_deg_init<<<(NNODES + 255) / 256, 256>>>();
    k_deg_count<<<(NEDGES + 255) / 256, 256>>>(edge_index);
    k_scan<<<1, 1024>>>();
    k_fill<<<(TOTE + 255) / 256, 256>>>(edge_index, edge_attr);

    for (int l = 0; l < NLAYERS; l++) {
        k_gemm_tma<<<dim3(NMCH, NJB), 256, GEMM_SMEM>>>(l, mlp_b + (size_t)l * EMB);
        if (l < NLAYERS - 1)
            k_aggr_frag<<<NNODES / 16, 256>>>(
                l, bn_rm + (size_t)l * EMB, bn_rv + (size_t)l * EMB,
                bn_g + (size_t)l * EMB, bn_b + (size_t)l * EMB);
        else
            k_aggr_last<<<(NNODES * 32 + 255) / 256, 256>>>(
                l, bn_rm + (size_t)l * EMB, bn_rv + (size_t)l * EMB,
                bn_g + (size_t)l * EMB, bn_b + (size_t)l * EMB);
    }

    k_qqk<<<BGR / 4, 256>>>(wk);
    k_attn<<<BGR, 256>>>();
    k_final<<<BGR / 4, 256>>>(ml_b, lg_b, ph1_b, ph2_w, ph2_b, out);
}

// round 16
// speedup vs baseline: 1.0319x; 1.0319x over previous
#include <cuda_runtime.h>
#include <cuda_bf16.h>
#include <math.h>
#include <stdint.h>

#define NNODES 50000
#define NPADM  50048
#define NMCH   391
#define NEDGES 200000
#define TOTE   (NEDGES + NNODES)
#define EMB    300
#define EMB4   75
#define NKT    19
#define DK     256
#define BGR    1000
#define NPER   50
#define NLAYERS 5
#define PADF   16
#define NJB    3
#define NTL    14

// ---------------- scratch (device globals) ----------------
__device__ float g_h[NNODES * EMB];
__device__ float g_hW[NNODES * EMB];
__device__ uint4 g_hfa_hi[NMCH * NKT * 8 * 32];
__device__ uint4 g_hfa_lo[NMCH * NKT * 8 * 32];
__device__ uint4 g_wfb[NLAYERS * NJB * NKT * NTL * 32];
__device__ float g_mf[BGR * EMB];
__device__ float g_ve_all[NLAYERS * 2 * EMB];
__device__ float g_Q[BGR * DK];
__device__ float g_qk[BGR * EMB];
__device__ float g_wsum[BGR * EMB];
__device__ float g_mean[BGR * EMB];
__device__ float g_wqt[EMB * DK];
__device__ float g_wvt[EMB * DK];
__device__ float g_mlt[EMB * DK];
__device__ float g_lgt[EMB * DK];
__device__ float g_ph1t[DK * 512];
// CSR
__device__ int g_deg[NNODES];
__device__ int g_off[NNODES + 1];
__device__ int g_cur[NNODES];
__device__ int g_csr_src[TOTE];
__device__ float2 g_csr_ea[TOTE];

// ---------------- helpers ----------------
__device__ __forceinline__ void split_pack(float v0, float v1, uint32_t& hi, uint32_t& lo)
{
    __nv_bfloat16 h0 = __float2bfloat16(v0);
    __nv_bfloat16 h1 = __float2bfloat16(v1);
    __nv_bfloat16 l0 = __float2bfloat16(v0 - __bfloat162float(h0));
    __nv_bfloat16 l1 = __float2bfloat16(v1 - __bfloat162float(h1));
    __nv_bfloat162 H = __halves2bfloat162(h0, h1);
    __nv_bfloat162 L = __halves2bfloat162(l0, l1);
    hi = *(uint32_t*)&H;
    lo = *(uint32_t*)&L;
}

__device__ __forceinline__ uint32_t smem_u32(const void* p) {
    uint32_t a;
    asm("{ .reg .u64 t; cvta.to.shared.u64 t, %1; cvt.u32.u64 %0, t; }" : "=r"(a) : "l"(p));
    return a;
}

#define MMA_BF16(d, a, b) asm volatile( \
    "mma.sync.aligned.m16n8k16.row.col.f32.bf16.bf16.f32 " \
    "{%0,%1,%2,%3},{%4,%5,%6,%7},{%8,%9},{%0,%1,%2,%3};\n" \
    : "+f"(d[0]), "+f"(d[1]), "+f"(d[2]), "+f"(d[3]) \
    : "r"((a)[0]), "r"((a)[1]), "r"((a)[2]), "r"((a)[3]), "r"((b)[0]), "r"((b)[1]))

#define LDS128(r, a) asm volatile( \
    "ld.shared.v4.b32 {%0,%1,%2,%3}, [%4];" \
    : "=r"((r)[0]), "=r"((r)[1]), "=r"((r)[2]), "=r"((r)[3]) : "r"(a))

#define MB_INIT(m) asm volatile("mbarrier.init.shared.b64 [%0], %1;" \
    :: "r"(m), "r"(1u) : "memory")
#define MB_EXPECT(m, n) asm volatile("mbarrier.arrive.expect_tx.shared.b64 _, [%0], %1;" \
    :: "r"(m), "r"((uint32_t)(n)) : "memory")
#define BULK_G2S(dst, src, sz, m) asm volatile( \
    "cp.async.bulk.shared::cluster.global.mbarrier::complete_tx::bytes [%0], [%1], %2, [%3];" \
    :: "r"(dst), "l"(src), "r"((uint32_t)(sz)), "r"(m) : "memory")

__device__ __forceinline__ void mbar_wait(uint32_t addr, uint32_t parity)
{
    uint32_t done;
    do {
        asm volatile(
            "{\n\t.reg .pred p;\n\t"
            "mbarrier.try_wait.parity.acquire.cta.shared::cta.b64 p, [%1], %2, 0x989680;\n\t"
            "selp.b32 %0,1,0,p;\n\t}"
            : "=r"(done) : "r"(addr), "r"(parity) : "memory");
    } while (!done);
}

#define HSW 332
__device__ __forceinline__ void write_frags_from_smem(float (*hs)[HSW], int mtile,
                                                      int warp, int lane)
{
    int gid = lane >> 2, tig = lane & 3;
    int mc = mtile >> 3, mt8 = mtile & 7;
    for (int kt = warp; kt < NKT; kt += 8) {
        int kb = kt * 16;
        float v00 = hs[gid][kb + 2 * tig],     v01 = hs[gid][kb + 2 * tig + 1];
        float v10 = hs[gid + 8][kb + 2 * tig], v11 = hs[gid + 8][kb + 2 * tig + 1];
        float v20 = hs[gid][kb + 8 + 2 * tig],     v21 = hs[gid][kb + 8 + 2 * tig + 1];
        float v30 = hs[gid + 8][kb + 8 + 2 * tig], v31 = hs[gid + 8][kb + 8 + 2 * tig + 1];
        uint4 Hi, Lo;
        split_pack(v00, v01, Hi.x, Lo.x);
        split_pack(v10, v11, Hi.y, Lo.y);
        split_pack(v20, v21, Hi.z, Lo.z);
        split_pack(v30, v31, Hi.w, Lo.w);
        size_t idx = (((size_t)mc * NKT + kt) * 8 + mt8) * 32 + lane;
        g_hfa_hi[idx] = Hi;
        g_hfa_lo[idx] = Lo;
    }
}

// ---------------- node init -> A fragments ----------------
__global__ void __launch_bounds__(256) k_init_frag(const int* __restrict__ x_type,
                                                   const float* __restrict__ x_feat,
                                                   const float* __restrict__ x_emb,
                                                   const float* __restrict__ x_weight)
{
    __shared__ float hs[16][HSW];
    int tid = threadIdx.x, warp = tid >> 5, lane = tid & 31;
    int base = blockIdx.x * 16;
#pragma unroll
    for (int i = 0; i < 2; i++) {
        int row = warp * 2 + i;
        int n = base + row;
        int t = __ldg(x_type + n);
#pragma unroll
        for (int ch = 0; ch < 3; ch++) {
            int c = lane + 32 * ch;
            if (c < EMB4) {
                float4 acc = __ldg((const float4*)(x_emb + (size_t)t * EMB) + c);
#pragma unroll
                for (int k = 0; k < PADF; k++) {
                    float f = __ldg(x_feat + (size_t)n * PADF + k);
                    float4 w = __ldg((const float4*)(x_weight + (size_t)k * EMB) + c);
                    acc.x = fmaf(f, w.x, acc.x); acc.y = fmaf(f, w.y, acc.y);
                    acc.z = fmaf(f, w.z, acc.z); acc.w = fmaf(f, w.w, acc.w);
                }
                *(float4*)&hs[row][4 * c] = acc;
            }
        }
        hs[row][300 + lane] = 0.f;
    }
    __syncthreads();
    write_frags_from_smem(hs, blockIdx.x, warp, lane);
}

// ---------------- weight split -> B fragments ----------------
__global__ void k_wsplit_frag(const float* __restrict__ mlp_w)
{
    int idx = blockIdx.x * blockDim.x + threadIdx.x;
    if (idx >= NLAYERS * NJB * NKT * NTL * 32) return;
    int lane = idx & 31;
    int ntl = (idx >> 5) % NTL;
    int kt = (idx >> 5) / NTL % NKT;
    int jblk = (idx >> 5) / (NTL * NKT) % NJB;
    int l = idx / (32 * NTL * NKT * NJB);
    int gid = lane >> 2, tig = lane & 3;
    int j = jblk * 112 + ntl * 8 + gid;
    int k0 = kt * 16 + 2 * tig;
    int k1 = k0 + 8;
    const float* W = mlp_w + (size_t)l * EMB * EMB + (size_t)j * EMB;
    float w00 = (j < EMB && k0 < EMB) ? __ldg(W + k0) : 0.f;
    float w01 = (j < EMB && k0 + 1 < EMB) ? __ldg(W + k0 + 1) : 0.f;
    float w10 = (j < EMB && k1 < EMB) ? __ldg(W + k1) : 0.f;
    float w11 = (j < EMB && k1 + 1 < EMB) ? __ldg(W + k1 + 1) : 0.f;
    uint4 o;
    split_pack(w00, w01, o.x, o.z);
    split_pack(w10, w11, o.y, o.w);
    g_wfb[idx] = o;
}

// ---------------- fused prework: mf | deg_init | zero_padfrag | ve_all | transpose ----
#define PR_MF0   0
#define PR_MF1   (BGR * EMB)                       // 300000
#define PR_DEG1  (PR_MF1 + NNODES)                 // 350000
#define PR_ZP1   (PR_DEG1 + NKT * 3 * 32)          // 351824
#define PR_VE0   ((PR_ZP1 + 31) & ~31)             // 351840 (warp aligned)
#define PR_VE1   (PR_VE0 + NLAYERS * 2 * EMB * 32) // 447840
#define PR_TR1   (PR_VE1 + 4 * DK * EMB + 512 * DK)
#define PR_TOTAL PR_TR1

__global__ void k_prep(const int* __restrict__ metal_type, const float* __restrict__ metal_feat,
                       const float* __restrict__ me1_w, const float* __restrict__ me1_b,
                       const float* __restrict__ me2,
                       const float* __restrict__ ew1, const float* __restrict__ mlp_w,
                       const float* __restrict__ wq, const float* __restrict__ wv,
                       const float* __restrict__ ml, const float* __restrict__ lg,
                       const float* __restrict__ ph1)
{
    int idx = blockIdx.x * blockDim.x + threadIdx.x;
    if (idx < PR_MF1) {
        // metal feature
        int b = idx / EMB, j = idx % EMB;
        float acc = __ldg(me1_b + j) + __ldg(me2 + (size_t)__ldg(metal_type + b) * EMB + j);
#pragma unroll
        for (int k = 0; k < 17; k++)
            acc = fmaf(__ldg(metal_feat + (size_t)b * 17 + k), __ldg(me1_w + (size_t)j * 17 + k), acc);
        g_mf[idx] = acc;
    } else if (idx < PR_DEG1) {
        g_deg[idx - PR_MF1] = 1;   // self-loop
    } else if (idx < PR_ZP1) {
        int i = idx - PR_DEG1;
        int lane = i & 31, mt8 = 5 + ((i >> 5) % 3), kt = (i >> 5) / 3;
        size_t o = (((size_t)390 * NKT + kt) * 8 + mt8) * 32 + lane;
        uint4 z = make_uint4(0, 0, 0, 0);
        g_hfa_hi[o] = z;
        g_hfa_lo[o] = z;
    } else if (idx >= PR_VE0 && idx < PR_VE1) {
        // edge vectors (warp per output)
        int i = idx - PR_VE0;
        int o = i >> 5, lane = i & 31;
        int l = o / (2 * EMB);
        int rem = o % (2 * EMB);
        int w = rem / EMB, col = rem % EMB;
        const float* e = ew1 + (size_t)l * 2 * EMB + (size_t)w * EMB;
        const float* wr = mlp_w + (size_t)l * EMB * EMB + (size_t)col * EMB;
        float s = 0.f;
        for (int k = lane; k < EMB; k += 32) s = fmaf(__ldg(e + k), __ldg(wr + k), s);
#pragma unroll
        for (int off = 16; off; off >>= 1) s += __shfl_xor_sync(0xffffffffu, s, off);
        if (lane == 0) g_ve_all[o] = s;
    } else if (idx >= PR_VE1 && idx < PR_TR1) {
        int i2 = idx - PR_VE1;
        const int SZ1 = DK * EMB;
        if (i2 < 4 * SZ1) {
            int w = i2 / SZ1, i = i2 % SZ1;
            int d = i / EMB, j = i % EMB;
            float v = (w == 0) ? wq[i] : (w == 1) ? wv[i] : (w == 2) ? ml[i] : lg[i];
            float* dst = (w == 0) ? g_wqt : (w == 1) ? g_wvt : (w == 2) ? g_mlt : g_lgt;
            dst[(size_t)j * DK + d] = v;
        } else {
            int i = i2 - 4 * SZ1;
            int o = i / DK, d = i % DK;
            g_ph1t[(size_t)d * 512 + o] = ph1[i];
        }
    }
}

// ---------------- CSR build ----------------
__global__ void k_deg_count(const int* __restrict__ eidx) {
    int e = blockIdx.x * blockDim.x + threadIdx.x;
    if (e < NEDGES) atomicAdd(&g_deg[__ldg(eidx + NEDGES + e)], 1);
}
__global__ void k_scan() {
    __shared__ int ps[1024];
    const int C = (NNODES + 1023) / 1024;
    int t = threadIdx.x;
    int base = t * C;
    int s = 0;
    for (int i = base; i < base + C && i < NNODES; i++) s += g_deg[i];
    ps[t] = s;
    __syncthreads();
    for (int off = 1; off < 1024; off <<= 1) {
        int v = (t >= off) ? ps[t - off] : 0;
        __syncthreads();
        ps[t] += v;
        __syncthreads();
    }
    int ex = (t == 0) ? 0 : ps[t - 1];
    for (int i = base; i < base + C && i < NNODES; i++) {
        g_off[i] = ex; g_cur[i] = ex;
        ex += g_deg[i];
    }
    if (t == 1023) g_off[NNODES] = TOTE;
}
__global__ void k_fill(const int* __restrict__ eidx, const float* __restrict__ eattr) {
    int idx = blockIdx.x * blockDim.x + threadIdx.x;
    if (idx >= TOTE) return;
    int src, col; float2 ea;
    if (idx < NEDGES) {
        src = __ldg(eidx + idx);
        col = __ldg(eidx + NEDGES + idx);
        ea = __ldg((const float2*)eattr + idx);
    } else {
        src = col = idx - NEDGES;
        ea = make_float2(0.f, 4.f);
    }
    int pos = atomicAdd(&g_cur[col], 1);
    g_csr_src[pos] = src;
    g_csr_ea[pos] = ea;
}

// ---------------- GEMM: one launch (391,3), block-uniform compile-time NTLW -------
#define STG    15360
#define MBOFF  (4 * STG)
#define GEMM_SMEM (MBOFF + 32)

template<int NTLW>
__device__ __forceinline__ void gemm_body(uint32_t sb, int layer, int jblk, int mc,
                                          const float* __restrict__ bias,
                                          int tid, int warp, int lane)
{
    int gid = lane >> 2, tig = lane & 3;
    int wm = warp & 3, wn = warp >> 2;
    int nbase = wn * NTLW;

#define ISSUE(kt_) do { \
    int s_ = (kt_) & 3; \
    uint32_t dst_ = sb + (uint32_t)s_ * STG; \
    uint32_t mb_ = sb + MBOFF + s_ * 8; \
    size_t ao_ = ((size_t)mc * NKT + (kt_)) * 256; \
    size_t bo_ = (((size_t)layer * NJB + jblk) * NKT + (kt_)) * (NTL * 32); \
    MB_EXPECT(mb_, STG); \
    BULK_G2S(dst_, g_hfa_hi + ao_, 4096, mb_); \
    BULK_G2S(dst_ + 4096, g_hfa_lo + ao_, 4096, mb_); \
    BULK_G2S(dst_ + 8192, g_wfb + bo_, 7168, mb_); \
} while (0)

    if (tid == 0) { ISSUE(0); ISSUE(1); ISSUE(2); }

    float acc[2][NTLW][4];
#pragma unroll
    for (int mt = 0; mt < 2; mt++)
#pragma unroll
        for (int nj = 0; nj < NTLW; nj++)
#pragma unroll
            for (int r = 0; r < 4; r++) acc[mt][nj][r] = 0.f;

    for (int kt = 0; kt < NKT; kt++) {
        uint32_t stg = sb + (uint32_t)(kt & 3) * STG;
        mbar_wait(sb + MBOFF + (kt & 3) * 8, (kt >> 2) & 1);
        // issue-early: stage (kt+3)&3 == (kt-1)&3 was fully consumed before the
        // __syncthreads at the end of iteration kt-1 (all warps passed it).
        if (tid == 0 && kt + 3 < NKT) ISSUE(kt + 3);

        uint32_t ah[2][4], al[2][4], bq[NTLW][4];
#pragma unroll
        for (int mt = 0; mt < 2; mt++) {
            uint32_t ao = ((uint32_t)(wm * 2 + mt) * 32 + lane) * 16;
            LDS128(ah[mt], stg + ao);
            LDS128(al[mt], stg + 4096 + ao);
        }
#pragma unroll
        for (int nj = 0; nj < NTLW; nj++) {
            uint32_t bo = ((uint32_t)(nbase + nj) * 32 + lane) * 16;
            LDS128(bq[nj], stg + 8192 + bo);
        }
#pragma unroll
        for (int mt = 0; mt < 2; mt++)
#pragma unroll
            for (int nj = 0; nj < NTLW; nj++) MMA_BF16(acc[mt][nj], ah[mt], bq[nj]);
#pragma unroll
        for (int mt = 0; mt < 2; mt++)
#pragma unroll
            for (int nj = 0; nj < NTLW; nj++) MMA_BF16(acc[mt][nj], al[mt], bq[nj]);
#pragma unroll
        for (int mt = 0; mt < 2; mt++)
#pragma unroll
            for (int nj = 0; nj < NTLW; nj++) MMA_BF16(acc[mt][nj], ah[mt], bq[nj] + 2);

        __syncthreads();
    }
#undef ISSUE

#pragma unroll
    for (int mt = 0; mt < 2; mt++) {
        int m = mc * 128 + (wm * 2 + mt) * 16 + gid;
#pragma unroll
        for (int nj = 0; nj < NTLW; nj++) {
            int j = jblk * 112 + (nbase + nj) * 8 + 2 * tig;
            if (j < EMB) {
                float b0 = __ldg(bias + j), b1 = __ldg(bias + j + 1);
                if (m < NNODES)
                    *(float2*)(g_hW + (size_t)m * EMB + j) =
                        make_float2(acc[mt][nj][0] + b0, acc[mt][nj][1] + b1);
                if (m + 8 < NNODES)
                    *(float2*)(g_hW + (size_t)(m + 8) * EMB + j) =
                        make_float2(acc[mt][nj][2] + b0, acc[mt][nj][3] + b1);
            }
        }
    }
}

__global__ void __launch_bounds__(256, 2) k_gemm_tma(int layer, const float* __restrict__ bias)
{
    extern __shared__ char smem[];
    uint32_t sb = smem_u32(smem);
    int tid = threadIdx.x, warp = tid >> 5, lane = tid & 31;
    int mc = blockIdx.x, jblk = blockIdx.y;

    if (tid == 0) {
#pragma unroll
        for (int s = 0; s < 4; s++) MB_INIT(sb + MBOFF + s * 8);
    }
    __syncthreads();

    if (jblk < 2) gemm_body<7>(sb, layer, jblk, mc, bias, tid, warp, lane);
    else          gemm_body<5>(sb, layer, jblk, mc, bias, tid, warp, lane);
}

// ---------------- aggregation + BN + relu -> A fragments (layers 0..3) ----------------
__global__ void __launch_bounds__(256) k_aggr_frag(int layer,
                                                   const float* __restrict__ rm,
                                                   const float* __restrict__ rv,
                                                   const float* __restrict__ gg,
                                                   const float* __restrict__ bb)
{
    __shared__ float hs[16][HSW];
    int tid = threadIdx.x, warp = tid >> 5, lane = tid & 31;
    int base = blockIdx.x * 16;
    const float4* ve4 = (const float4*)(g_ve_all + (size_t)layer * 2 * EMB);

    float4 e0[3], e1[3], bm[3], bv[3], bg[3], bbb[3];
#pragma unroll
    for (int i = 0; i < 3; i++) {
        int c = lane + 32 * i;
        if (c < EMB4) {
            e0[i] = __ldg(ve4 + c); e1[i] = __ldg(ve4 + EMB4 + c);
            bm[i] = __ldg((const float4*)rm + c);
            bv[i] = __ldg((const float4*)rv + c);
            bg[i] = __ldg((const float4*)gg + c);
            bbb[i] = __ldg((const float4*)bb + c);
        }
    }
#pragma unroll
    for (int ni = 0; ni < 2; ni++) {
        int row = warp * 2 + ni;
        int gw = base + row;
        float4 acc[3];
#pragma unroll
        for (int i = 0; i < 3; i++) acc[i] = make_float4(0.f, 0.f, 0.f, 0.f);
        int beg = g_off[gw], end = g_off[gw + 1];
        for (int e = beg; e < end; e++) {
            int src = g_csr_src[e];
            float2 ea = g_csr_ea[e];
            const float4* rowp = (const float4*)(g_hW + (size_t)src * EMB);
#pragma unroll
            for (int i = 0; i < 3; i++) {
                int c = lane + 32 * i;
                if (c < EMB4) {
                    float4 x = rowp[c];
                    acc[i].x += fmaxf(fmaf(ea.y, e1[i].x, fmaf(ea.x, e0[i].x, x.x)), 0.f);
                    acc[i].y += fmaxf(fmaf(ea.y, e1[i].y, fmaf(ea.x, e0[i].y, x.y)), 0.f);
                    acc[i].z += fmaxf(fmaf(ea.y, e1[i].z, fmaf(ea.x, e0[i].z, x.z)), 0.f);
                    acc[i].w += fmaxf(fmaf(ea.y, e1[i].w, fmaf(ea.x, e0[i].w, x.w)), 0.f);
                }
            }
        }
#pragma unroll
        for (int i = 0; i < 3; i++) {
            int c = lane + 32 * i;
            if (c < EMB4) {
                float4 y;
                y.x = fmaxf((acc[i].x - bm[i].x) * rsqrtf(bv[i].x + 1e-5f) * bg[i].x + bbb[i].x, 0.f);
                y.y = fmaxf((acc[i].y - bm[i].y) * rsqrtf(bv[i].y + 1e-5f) * bg[i].y + bbb[i].y, 0.f);
                y.z = fmaxf((acc[i].z - bm[i].z) * rsqrtf(bv[i].z + 1e-5f) * bg[i].z + bbb[i].z, 0.f);
                y.w = fmaxf((acc[i].w - bm[i].w) * rsqrtf(bv[i].w + 1e-5f) * bg[i].w + bbb[i].w, 0.f);
                *(float4*)&hs[row][4 * c] = y;
            }
        }
        hs[row][300 + lane] = 0.f;
    }
    __syncthreads();
    write_frags_from_smem(hs, blockIdx.x, warp, lane);
}

// ---------------- last layer aggregation + BN (no relu) -> g_h linear ----------------
__global__ void __launch_bounds__(256) k_aggr_last(int layer,
                                                   const float* __restrict__ rm,
                                                   const float* __restrict__ rv,
                                                   const float* __restrict__ gg,
                                                   const float* __restrict__ bb)
{
    int gw = (blockIdx.x * blockDim.x + threadIdx.x) >> 5;
    if (gw >= NNODES) return;
    int lane = threadIdx.x & 31;
    const float4* ve4 = (const float4*)(g_ve_all + (size_t)layer * 2 * EMB);

    float4 acc[3], e0[3], e1[3];
#pragma unroll
    for (int i = 0; i < 3; i++) {
        acc[i] = make_float4(0.f, 0.f, 0.f, 0.f);
        int c = lane + 32 * i;
        if (c < EMB4) { e0[i] = __ldg(ve4 + c); e1[i] = __ldg(ve4 + EMB4 + c); }
    }
    int beg = g_off[gw], end = g_off[gw + 1];
    for (int e = beg; e < end; e++) {
        int src = g_csr_src[e];
        float2 ea = g_csr_ea[e];
        const float4* row = (const float4*)(g_hW + (size_t)src * EMB);
#pragma unroll
        for (int i = 0; i < 3; i++) {
            int c = lane + 32 * i;
            if (c < EMB4) {
                float4 x = row[c];
                acc[i].x += fmaxf(fmaf(ea.y, e1[i].x, fmaf(ea.x, e0[i].x, x.x)), 0.f);
                acc[i].y += fmaxf(fmaf(ea.y, e1[i].y, fmaf(ea.x, e0[i].y, x.y)), 0.f);
                acc[i].z += fmaxf(fmaf(ea.y, e1[i].z, fmaf(ea.x, e0[i].z, x.z)), 0.f);
                acc[i].w += fmaxf(fmaf(ea.y, e1[i].w, fmaf(ea.x, e0[i].w, x.w)), 0.f);
            }
        }
    }
#pragma unroll
    for (int i = 0; i < 3; i++) {
        int c = lane + 32 * i;
        if (c < EMB4) {
            float4 m = __ldg((const float4*)rm + c);
            float4 v = __ldg((const float4*)rv + c);
            float4 g4 = __ldg((const float4*)gg + c);
            float4 b4 = __ldg((const float4*)bb + c);
            float4 y;
            y.x = (acc[i].x - m.x) * rsqrtf(v.x + 1e-5f) * g4.x + b4.x;
            y.y = (acc[i].y - m.y) * rsqrtf(v.y + 1e-5f) * g4.y + b4.y;
            y.z = (acc[i].z - m.z) * rsqrtf(v.z + 1e-5f) * g4.z + b4.z;
            y.w = (acc[i].w - m.w) * rsqrtf(v.w + 1e-5f) * g4.w + b4.w;
            ((float4*)(g_h + (size_t)gw * EMB))[c] = y;
        }
    }
}

// ---------------- readout ----------------
__global__ void k_q()
{
    __shared__ float mfs[4][EMB];
    int b0 = blockIdx.x * 4, tid = threadIdx.x;
    for (int i = tid; i < 4 * EMB; i += 256)
        mfs[i / EMB][i % EMB] = g_mf[(size_t)(b0 + i / EMB) * EMB + i % EMB];
    __syncthreads();
    float acc[4] = {0.f, 0.f, 0.f, 0.f};
    for (int j = 0; j < EMB; j++) {
        float w = g_wqt[(size_t)j * DK + tid];
#pragma unroll
        for (int g = 0; g < 4; g++) acc[g] = fmaf(mfs[g][j], w, acc[g]);
    }
#pragma unroll
    for (int g = 0; g < 4; g++) g_Q[(size_t)(b0 + g) * DK + tid] = acc[g];
}

__global__ void k_qk(const float* __restrict__ wk)
{
    __shared__ float Qs[4][DK];
    int b0 = blockIdx.x * 4, tid = threadIdx.x;
    for (int i = tid; i < 4 * DK; i += 320)
        Qs[i / DK][i % DK] = g_Q[(size_t)(b0 + i / DK) * DK + i % DK];
    __syncthreads();
    if (tid < EMB) {
        float acc[4] = {0.f, 0.f, 0.f, 0.f};
        for (int d = 0; d < DK; d++) {
            float w = __ldg(wk + (size_t)d * EMB + tid);
#pragma unroll
            for (int g = 0; g < 4; g++) acc[g] = fmaf(Qs[g][d], w, acc[g]);
        }
#pragma unroll
        for (int g = 0; g < 4; g++) g_qk[(size_t)(b0 + g) * EMB + tid] = acc[g];
    }
}

__global__ void k_attn()
{
    __shared__ float qks[EMB];
    __shared__ float sc[NPER];
    __shared__ float p[NPER];
    int b = blockIdx.x, tid = threadIdx.x;
    for (int i = tid; i < EMB; i += 256) qks[i] = g_qk[(size_t)b * EMB + i];
    __syncthreads();
    int warp = tid >> 5, lane = tid & 31;
    const float* hb = g_h + (size_t)b * NPER * EMB;
    for (int k = warp; k < NPER; k += 8) {
        float s = 0.f;
        for (int i = lane; i < EMB; i += 32) s = fmaf(qks[i], hb[(size_t)k * EMB + i], s);
#pragma unroll
        for (int off = 16; off; off >>= 1) s += __shfl_xor_sync(0xffffffffu, s, off);
        if (lane == 0) sc[k] = s * (1.0f / 16.0f);
    }
    __syncthreads();
    if (tid == 0) {
        float mx = -1e30f;
        for (int k = 0; k < NPER; k++) mx = fmaxf(mx, sc[k]);
        float ssum = 0.f;
        for (int k = 0; k < NPER; k++) { float e = expf(sc[k] - mx); p[k] = e; ssum += e; }
        float inv = 1.f / ssum;
        for (int k = 0; k < NPER; k++) p[k] *= inv;
    }
    __syncthreads();
    for (int j = tid; j < EMB; j += 256) {
        float ws = 0.f, mn = 0.f;
        for (int k = 0; k < NPER; k++) {
            float v = hb[(size_t)k * EMB + j];
            ws = fmaf(p[k], v, ws); mn += v;
        }
        g_wsum[(size_t)b * EMB + j] = ws;
        g_mean[(size_t)b * EMB + j] = mn * (1.0f / NPER);
    }
}

__global__ void k_final(const float* __restrict__ ml_b, const float* __restrict__ lg_b,
                        const float* __restrict__ ph1_b, const float* __restrict__ ph2_w,
                        const float* __restrict__ ph2_b, float* __restrict__ out)
{
    __shared__ float ws[4][EMB], mfs[4][EMB], mns[4][EMB];
    __shared__ float feat[4][DK];
    __shared__ float red[256];
    int b0 = blockIdx.x * 4, tid = threadIdx.x;
    for (int i = tid; i < 4 * EMB; i += 256) {
        int g = i / EMB, j = i % EMB;
        ws[g][j]  = g_wsum[(size_t)(b0 + g) * EMB + j];
        mfs[g][j] = g_mf[(size_t)(b0 + g) * EMB + j];
        mns[g][j] = g_mean[(size_t)(b0 + g) * EMB + j];
    }
    __syncthreads();
    int d = tid;
    float a[4], m2[4], lg[4];
    float mb = __ldg(ml_b + d), lb = __ldg(lg_b + d);
#pragma unroll
    for (int g = 0; g < 4; g++) { a[g] = 0.f; m2[g] = mb; lg[g] = lb; }
    for (int k = 0; k < EMB; k++) {
        float wv_ = g_wvt[(size_t)k * DK + d];
        float ml_ = g_mlt[(size_t)k * DK + d];
        float lg_ = g_lgt[(size_t)k * DK + d];
#pragma unroll
        for (int g = 0; g < 4; g++) {
            a[g]  = fmaf(wv_, ws[g][k],  a[g]);
            m2[g] = fmaf(ml_, mfs[g][k], m2[g]);
            lg[g] = fmaf(lg_, mns[g][k], lg[g]);
        }
    }
#pragma unroll
    for (int g = 0; g < 4; g++)
        feat[g][d] = fmaxf(a[g], 0.f) + fmaxf(m2[g], 0.f) + fmaxf(lg[g], 0.f);
    __syncthreads();
    float part[4] = {0.f, 0.f, 0.f, 0.f};
#pragma unroll
    for (int rep = 0; rep < 2; rep++) {
        int o = tid + rep * 256;
        float t[4];
        float pb = __ldg(ph1_b + o);
#pragma unroll
        for (int g = 0; g < 4; g++) t[g] = pb;
        for (int k = 0; k < DK; k++) {
            float w = g_ph1t[(size_t)k * 512 + o];
#pragma unroll
            for (int g = 0; g < 4; g++) t[g] = fmaf(w, feat[g][k], t[g]);
        }
        float p2 = __ldg(ph2_w + o);
#pragma unroll
        for (int g = 0; g < 4; g++) {
            float x = t[g];
            float sp = (x > 20.f) ? x : log1pf(expf(x));
            part[g] = fmaf(sp, p2, part[g]);
        }
    }
    for (int g = 0; g < 4; g++) {
        red[tid] = part[g];
        __syncthreads();
        for (int s = 128; s; s >>= 1) {
            if (tid < s) red[tid] += red[tid + s];
            __syncthreads();
        }
        if (tid == 0) out[b0 + g] = red[0] + __ldg(ph2_b);
        __syncthreads();
    }
}

// ---------------- launch ----------------
extern "C" void kernel_launch(void* const* d_in, const int* in_sizes, int n_in,
                              void* d_out, int out_size)
{
    const int*   x_type     = (const int*)d_in[0];
    const float* x_feat     = (const float*)d_in[1];
    const int*   edge_index = (const int*)d_in[2];
    const float* edge_attr  = (const float*)d_in[3];
    const int*   metal_type = (const int*)d_in[4];
    const float* metal_feat = (const float*)d_in[5];
    const float* x_emb      = (const float*)d_in[6];
    const float* x_weight   = (const float*)d_in[7];
    const float* ew1        = (const float*)d_in[8];
    const float* mlp_w      = (const float*)d_in[9];
    const float* mlp_b      = (const float*)d_in[10];
    const float* bn_g       = (const float*)d_in[11];
    const float* bn_b       = (const float*)d_in[12];
    const float* bn_rm      = (const float*)d_in[13];
    const float* bn_rv      = (const float*)d_in[14];
    const float* me1_w      = (const float*)d_in[15];
    const float* me1_b      = (const float*)d_in[16];
    const float* me2        = (const float*)d_in[17];
    const float* wq         = (const float*)d_in[18];
    const float* wk         = (const float*)d_in[19];
    const float* wv         = (const float*)d_in[20];
    const float* ml_w       = (const float*)d_in[21];
    const float* ml_b       = (const float*)d_in[22];
    const float* lg_w       = (const float*)d_in[23];
    const float* lg_b       = (const float*)d_in[24];
    const float* ph1_w      = (const float*)d_in[25];
    const float* ph1_b      = (const float*)d_in[26];
    const float* ph2_w      = (const float*)d_in[27];
    const float* ph2_b      = (const float*)d_in[28];
    float* out = (float*)d_out;

    cudaFuncSetAttribute(k_gemm_tma, cudaFuncAttributeMaxDynamicSharedMemorySize, GEMM_SMEM);

    k_init_frag<<<NNODES / 16, 256>>>(x_type, x_feat, x_emb, x_weight);
    k_wsplit_frag<<<(NLAYERS * NJB * NKT * NTL * 32 + 255) / 256, 256>>>(mlp_w);
    k_prep<<<(PR_TOTAL + 255) / 256, 256>>>(metal_type, metal_feat, me1_w, me1_b, me2,
                                            ew1, mlp_w, wq, wv, ml_w, lg_w, ph1_w);
    k_deg_count<<<(NEDGES + 255) / 256, 256>>>(edge_index);
    k_scan<<<1, 1024>>>();
    k_fill<<<(TOTE + 255) / 256, 256>>>(edge_index, edge_attr);

    for (int l = 0; l < NLAYERS; l++) {
        k_gemm_tma<<<dim3(NMCH, NJB), 256, GEMM_SMEM>>>(l, mlp_b + (size_t)l * EMB);
        if (l < NLAYERS - 1)
            k_aggr_frag<<<NNODES / 16, 256>>>(
                l, bn_rm + (size_t)l * EMB, bn_rv + (size_t)l * EMB,
                bn_g + (size_t)l * EMB, bn_b + (size_t)l * EMB);
        else
            k_aggr_last<<<(NNODES * 32 + 255) / 256, 256>>>(
                l, bn_rm + (size_t)l * EMB, bn_rv + (size_t)l * EMB,
                bn_g + (size_t)l * EMB, bn_b + (size_t)l * EMB);
    }

    k_q<<<BGR / 4, 256>>>();
    k_qk<<<BGR / 4, 320>>>(wk);
    k_attn<<<BGR, 256>>>();
    k_final<<<BGR / 4, 256>>>(ml_b, lg_b, ph1_b, ph2_w, ph2_b, out);
}

// round 17
// speedup vs baseline: 1.0886x; 1.0550x over previous
#include <cuda_runtime.h>
#include <cuda_bf16.h>
#include <math.h>
#include <stdint.h>

#define NNODES 50000
#define NPADM  50048
#define NMCH   391
#define NEDGES 200000
#define TOTE   (NEDGES + NNODES)
#define EMB    300
#define EMB4   75
#define NKT    19
#define DK     256
#define BGR    1000
#define NPER   50
#define NLAYERS 5
#define PADF   16
#define NJB    3
#define NTL    14

// ---------------- scratch (device globals) ----------------
__device__ float g_h[NNODES * EMB];
__device__ float g_hW[NNODES * EMB];
__device__ uint4 g_hfa_hi[NMCH * NKT * 8 * 32];
__device__ uint4 g_hfa_lo[NMCH * NKT * 8 * 32];
__device__ uint4 g_wfb[NLAYERS * NJB * NKT * NTL * 32];
__device__ float g_mf[BGR * EMB];
__device__ float g_ve_all[NLAYERS * 2 * EMB];
__device__ float g_Q[BGR * DK];
__device__ float g_qk[BGR * EMB];
__device__ float g_wsum[BGR * EMB];
__device__ float g_mean[BGR * EMB];
__device__ float g_wqt[EMB * DK];
__device__ float g_wvt[EMB * DK];
__device__ float g_mlt[EMB * DK];
__device__ float g_lgt[EMB * DK];
__device__ float g_ph1t[DK * 512];
// CSR
__device__ int g_deg[NNODES];
__device__ int g_off[NNODES + 1];
__device__ int g_cur[NNODES];
__device__ int g_csr_src[TOTE];
__device__ float2 g_csr_ea[TOTE];

// ---------------- helpers ----------------
__device__ __forceinline__ void split_pack(float v0, float v1, uint32_t& hi, uint32_t& lo)
{
    __nv_bfloat16 h0 = __float2bfloat16(v0);
    __nv_bfloat16 h1 = __float2bfloat16(v1);
    __nv_bfloat16 l0 = __float2bfloat16(v0 - __bfloat162float(h0));
    __nv_bfloat16 l1 = __float2bfloat16(v1 - __bfloat162float(h1));
    __nv_bfloat162 H = __halves2bfloat162(h0, h1);
    __nv_bfloat162 L = __halves2bfloat162(l0, l1);
    hi = *(uint32_t*)&H;
    lo = *(uint32_t*)&L;
}

__device__ __forceinline__ uint32_t smem_u32(const void* p) {
    uint32_t a;
    asm("{ .reg .u64 t; cvta.to.shared.u64 t, %1; cvt.u32.u64 %0, t; }" : "=r"(a) : "l"(p));
    return a;
}

#define MMA_BF16(d, a, b) asm volatile( \
    "mma.sync.aligned.m16n8k16.row.col.f32.bf16.bf16.f32 " \
    "{%0,%1,%2,%3},{%4,%5,%6,%7},{%8,%9},{%0,%1,%2,%3};\n" \
    : "+f"(d[0]), "+f"(d[1]), "+f"(d[2]), "+f"(d[3]) \
    : "r"((a)[0]), "r"((a)[1]), "r"((a)[2]), "r"((a)[3]), "r"((b)[0]), "r"((b)[1]))

#define LDS128(r, a) asm volatile( \
    "ld.shared.v4.b32 {%0,%1,%2,%3}, [%4];" \
    : "=r"((r)[0]), "=r"((r)[1]), "=r"((r)[2]), "=r"((r)[3]) : "r"(a))

#define MB_INIT(m) asm volatile("mbarrier.init.shared.b64 [%0], %1;" \
    :: "r"(m), "r"(1u) : "memory")
#define MB_EXPECT(m, n) asm volatile("mbarrier.arrive.expect_tx.shared.b64 _, [%0], %1;" \
    :: "r"(m), "r"((uint32_t)(n)) : "memory")
#define BULK_G2S(dst, src, sz, m) asm volatile( \
    "cp.async.bulk.shared::cluster.global.mbarrier::complete_tx::bytes [%0], [%1], %2, [%3];" \
    :: "r"(dst), "l"(src), "r"((uint32_t)(sz)), "r"(m) : "memory")

__device__ __forceinline__ void mbar_wait(uint32_t addr, uint32_t parity)
{
    uint32_t done;
    do {
        asm volatile(
            "{\n\t.reg .pred p;\n\t"
            "mbarrier.try_wait.parity.acquire.cta.shared::cta.b64 p, [%1], %2, 0x989680;\n\t"
            "selp.b32 %0,1,0,p;\n\t}"
            : "=r"(done) : "r"(addr), "r"(parity) : "memory");
    } while (!done);
}

#define HSW 332
__device__ __forceinline__ void write_frags_from_smem(float (*hs)[HSW], int mtile,
                                                      int warp, int lane)
{
    int gid = lane >> 2, tig = lane & 3;
    int mc = mtile >> 3, mt8 = mtile & 7;
    for (int kt = warp; kt < NKT; kt += 8) {
        int kb = kt * 16;
        float v00 = hs[gid][kb + 2 * tig],     v01 = hs[gid][kb + 2 * tig + 1];
        float v10 = hs[gid + 8][kb + 2 * tig], v11 = hs[gid + 8][kb + 2 * tig + 1];
        float v20 = hs[gid][kb + 8 + 2 * tig],     v21 = hs[gid][kb + 8 + 2 * tig + 1];
        float v30 = hs[gid + 8][kb + 8 + 2 * tig], v31 = hs[gid + 8][kb + 8 + 2 * tig + 1];
        uint4 Hi, Lo;
        split_pack(v00, v01, Hi.x, Lo.x);
        split_pack(v10, v11, Hi.y, Lo.y);
        split_pack(v20, v21, Hi.z, Lo.z);
        split_pack(v30, v31, Hi.w, Lo.w);
        size_t idx = (((size_t)mc * NKT + kt) * 8 + mt8) * 32 + lane;
        g_hfa_hi[idx] = Hi;
        g_hfa_lo[idx] = Lo;
    }
}

// ---------------- node init -> A fragments ----------------
__global__ void __launch_bounds__(256) k_init_frag(const int* __restrict__ x_type,
                                                   const float* __restrict__ x_feat,
                                                   const float* __restrict__ x_emb,
                                                   const float* __restrict__ x_weight)
{
    __shared__ float hs[16][HSW];
    int tid = threadIdx.x, warp = tid >> 5, lane = tid & 31;
    int base = blockIdx.x * 16;
#pragma unroll
    for (int i = 0; i < 2; i++) {
        int row = warp * 2 + i;
        int n = base + row;
        int t = __ldg(x_type + n);
#pragma unroll
        for (int ch = 0; ch < 3; ch++) {
            int c = lane + 32 * ch;
            if (c < EMB4) {
                float4 acc = __ldg((const float4*)(x_emb + (size_t)t * EMB) + c);
#pragma unroll
                for (int k = 0; k < PADF; k++) {
                    float f = __ldg(x_feat + (size_t)n * PADF + k);
                    float4 w = __ldg((const float4*)(x_weight + (size_t)k * EMB) + c);
                    acc.x = fmaf(f, w.x, acc.x); acc.y = fmaf(f, w.y, acc.y);
                    acc.z = fmaf(f, w.z, acc.z); acc.w = fmaf(f, w.w, acc.w);
                }
                *(float4*)&hs[row][4 * c] = acc;
            }
        }
        hs[row][300 + lane] = 0.f;
    }
    __syncthreads();
    write_frags_from_smem(hs, blockIdx.x, warp, lane);
}

// ---------------- weight split -> B fragments ----------------
__global__ void k_wsplit_frag(const float* __restrict__ mlp_w)
{
    int idx = blockIdx.x * blockDim.x + threadIdx.x;
    if (idx >= NLAYERS * NJB * NKT * NTL * 32) return;
    int lane = idx & 31;
    int ntl = (idx >> 5) % NTL;
    int kt = (idx >> 5) / NTL % NKT;
    int jblk = (idx >> 5) / (NTL * NKT) % NJB;
    int l = idx / (32 * NTL * NKT * NJB);
    int gid = lane >> 2, tig = lane & 3;
    int j = jblk * 112 + ntl * 8 + gid;
    int k0 = kt * 16 + 2 * tig;
    int k1 = k0 + 8;
    const float* W = mlp_w + (size_t)l * EMB * EMB + (size_t)j * EMB;
    float w00 = (j < EMB && k0 < EMB) ? __ldg(W + k0) : 0.f;
    float w01 = (j < EMB && k0 + 1 < EMB) ? __ldg(W + k0 + 1) : 0.f;
    float w10 = (j < EMB && k1 < EMB) ? __ldg(W + k1) : 0.f;
    float w11 = (j < EMB && k1 + 1 < EMB) ? __ldg(W + k1 + 1) : 0.f;
    uint4 o;
    split_pack(w00, w01, o.x, o.z);
    split_pack(w10, w11, o.y, o.w);
    g_wfb[idx] = o;
}

// ---------------- fused prework: mf | deg_init | zero_padfrag | ve_all | transpose ----
#define PR_MF0   0
#define PR_MF1   (BGR * EMB)
#define PR_DEG1  (PR_MF1 + NNODES)
#define PR_ZP1   (PR_DEG1 + NKT * 3 * 32)
#define PR_VE0   ((PR_ZP1 + 31) & ~31)
#define PR_VE1   (PR_VE0 + NLAYERS * 2 * EMB * 32)
#define PR_TR1   (PR_VE1 + 4 * DK * EMB + 512 * DK)
#define PR_TOTAL PR_TR1

__global__ void k_prep(const int* __restrict__ metal_type, const float* __restrict__ metal_feat,
                       const float* __restrict__ me1_w, const float* __restrict__ me1_b,
                       const float* __restrict__ me2,
                       const float* __restrict__ ew1, const float* __restrict__ mlp_w,
                       const float* __restrict__ wq, const float* __restrict__ wv,
                       const float* __restrict__ ml, const float* __restrict__ lg,
                       const float* __restrict__ ph1)
{
    int idx = blockIdx.x * blockDim.x + threadIdx.x;
    if (idx < PR_MF1) {
        int b = idx / EMB, j = idx % EMB;
        float acc = __ldg(me1_b + j) + __ldg(me2 + (size_t)__ldg(metal_type + b) * EMB + j);
#pragma unroll
        for (int k = 0; k < 17; k++)
            acc = fmaf(__ldg(metal_feat + (size_t)b * 17 + k), __ldg(me1_w + (size_t)j * 17 + k), acc);
        g_mf[idx] = acc;
    } else if (idx < PR_DEG1) {
        g_deg[idx - PR_MF1] = 1;
    } else if (idx < PR_ZP1) {
        int i = idx - PR_DEG1;
        int lane = i & 31, mt8 = 5 + ((i >> 5) % 3), kt = (i >> 5) / 3;
        size_t o = (((size_t)390 * NKT + kt) * 8 + mt8) * 32 + lane;
        uint4 z = make_uint4(0, 0, 0, 0);
        g_hfa_hi[o] = z;
        g_hfa_lo[o] = z;
    } else if (idx >= PR_VE0 && idx < PR_VE1) {
        int i = idx - PR_VE0;
        int o = i >> 5, lane = i & 31;
        int l = o / (2 * EMB);
        int rem = o % (2 * EMB);
        int w = rem / EMB, col = rem % EMB;
        const float* e = ew1 + (size_t)l * 2 * EMB + (size_t)w * EMB;
        const float* wr = mlp_w + (size_t)l * EMB * EMB + (size_t)col * EMB;
        float s = 0.f;
        for (int k = lane; k < EMB; k += 32) s = fmaf(__ldg(e + k), __ldg(wr + k), s);
#pragma unroll
        for (int off = 16; off; off >>= 1) s += __shfl_xor_sync(0xffffffffu, s, off);
        if (lane == 0) g_ve_all[o] = s;
    } else if (idx >= PR_VE1 && idx < PR_TR1) {
        int i2 = idx - PR_VE1;
        const int SZ1 = DK * EMB;
        if (i2 < 4 * SZ1) {
            int w = i2 / SZ1, i = i2 % SZ1;
            int d = i / EMB, j = i % EMB;
            float v = (w == 0) ? wq[i] : (w == 1) ? wv[i] : (w == 2) ? ml[i] : lg[i];
            float* dst = (w == 0) ? g_wqt : (w == 1) ? g_wvt : (w == 2) ? g_mlt : g_lgt;
            dst[(size_t)j * DK + d] = v;
        } else {
            int i = i2 - 4 * SZ1;
            int o = i / DK, d = i % DK;
            g_ph1t[(size_t)d * 512 + o] = ph1[i];
        }
    }
}

// ---------------- CSR build ----------------
__global__ void k_deg_count(const int* __restrict__ eidx) {
    int e = blockIdx.x * blockDim.x + threadIdx.x;
    if (e < NEDGES) atomicAdd(&g_deg[__ldg(eidx + NEDGES + e)], 1);
}
__global__ void k_scan() {
    __shared__ int ps[1024];
    const int C = (NNODES + 1023) / 1024;
    int t = threadIdx.x;
    int base = t * C;
    int s = 0;
    for (int i = base; i < base + C && i < NNODES; i++) s += g_deg[i];
    ps[t] = s;
    __syncthreads();
    for (int off = 1; off < 1024; off <<= 1) {
        int v = (t >= off) ? ps[t - off] : 0;
        __syncthreads();
        ps[t] += v;
        __syncthreads();
    }
    int ex = (t == 0) ? 0 : ps[t - 1];
    for (int i = base; i < base + C && i < NNODES; i++) {
        g_off[i] = ex; g_cur[i] = ex;
        ex += g_deg[i];
    }
    if (t == 1023) g_off[NNODES] = TOTE;
}
__global__ void k_fill(const int* __restrict__ eidx, const float* __restrict__ eattr) {
    int idx = blockIdx.x * blockDim.x + threadIdx.x;
    if (idx >= TOTE) return;
    int src, col; float2 ea;
    if (idx < NEDGES) {
        src = __ldg(eidx + idx);
        col = __ldg(eidx + NEDGES + idx);
        ea = __ldg((const float2*)eattr + idx);
    } else {
        src = col = idx - NEDGES;
        ea = make_float2(0.f, 4.f);
    }
    int pos = atomicAdd(&g_cur[col], 1);
    g_csr_src[pos] = src;
    g_csr_ea[pos] = ea;
}

// ---------------- GEMM: one launch (391,3), block-uniform compile-time NTLW -------
#define STG    15360
#define MBOFF  (4 * STG)
#define GEMM_SMEM (MBOFF + 32)

template<int NTLW>
__device__ __forceinline__ void gemm_body(uint32_t sb, int layer, int jblk, int mc,
                                          const float* __restrict__ bias,
                                          int tid, int warp, int lane)
{
    int gid = lane >> 2, tig = lane & 3;
    int wm = warp & 3, wn = warp >> 2;
    int nbase = wn * NTLW;

#define ISSUE(kt_) do { \
    int s_ = (kt_) & 3; \
    uint32_t dst_ = sb + (uint32_t)s_ * STG; \
    uint32_t mb_ = sb + MBOFF + s_ * 8; \
    size_t ao_ = ((size_t)mc * NKT + (kt_)) * 256; \
    size_t bo_ = (((size_t)layer * NJB + jblk) * NKT + (kt_)) * (NTL * 32); \
    MB_EXPECT(mb_, STG); \
    BULK_G2S(dst_, g_hfa_hi + ao_, 4096, mb_); \
    BULK_G2S(dst_ + 4096, g_hfa_lo + ao_, 4096, mb_); \
    BULK_G2S(dst_ + 8192, g_wfb + bo_, 7168, mb_); \
} while (0)

    if (tid == 0) { ISSUE(0); ISSUE(1); ISSUE(2); }

    float acc[2][NTLW][4];
#pragma unroll
    for (int mt = 0; mt < 2; mt++)
#pragma unroll
        for (int nj = 0; nj < NTLW; nj++)
#pragma unroll
            for (int r = 0; r < 4; r++) acc[mt][nj][r] = 0.f;

    for (int kt = 0; kt < NKT; kt++) {
        uint32_t stg = sb + (uint32_t)(kt & 3) * STG;
        mbar_wait(sb + MBOFF + (kt & 3) * 8, (kt >> 2) & 1);
        if (tid == 0 && kt + 3 < NKT) ISSUE(kt + 3);

        uint32_t ah[2][4], al[2][4], bq[NTLW][4];
#pragma unroll
        for (int mt = 0; mt < 2; mt++) {
            uint32_t ao = ((uint32_t)(wm * 2 + mt) * 32 + lane) * 16;
            LDS128(ah[mt], stg + ao);
            LDS128(al[mt], stg + 4096 + ao);
        }
#pragma unroll
        for (int nj = 0; nj < NTLW; nj++) {
            uint32_t bo = ((uint32_t)(nbase + nj) * 32 + lane) * 16;
            LDS128(bq[nj], stg + 8192 + bo);
        }
#pragma unroll
        for (int mt = 0; mt < 2; mt++)
#pragma unroll
            for (int nj = 0; nj < NTLW; nj++) MMA_BF16(acc[mt][nj], ah[mt], bq[nj]);
#pragma unroll
        for (int mt = 0; mt < 2; mt++)
#pragma unroll
            for (int nj = 0; nj < NTLW; nj++) MMA_BF16(acc[mt][nj], al[mt], bq[nj]);
#pragma unroll
        for (int mt = 0; mt < 2; mt++)
#pragma unroll
            for (int nj = 0; nj < NTLW; nj++) MMA_BF16(acc[mt][nj], ah[mt], bq[nj] + 2);

        __syncthreads();
    }
#undef ISSUE

#pragma unroll
    for (int mt = 0; mt < 2; mt++) {
        int m = mc * 128 + (wm * 2 + mt) * 16 + gid;
#pragma unroll
        for (int nj = 0; nj < NTLW; nj++) {
            int j = jblk * 112 + (nbase + nj) * 8 + 2 * tig;
            if (j < EMB) {
                float b0 = __ldg(bias + j), b1 = __ldg(bias + j + 1);
                if (m < NNODES)
                    *(float2*)(g_hW + (size_t)m * EMB + j) =
                        make_float2(acc[mt][nj][0] + b0, acc[mt][nj][1] + b1);
                if (m + 8 < NNODES)
                    *(float2*)(g_hW + (size_t)(m + 8) * EMB + j) =
                        make_float2(acc[mt][nj][2] + b0, acc[mt][nj][3] + b1);
            }
        }
    }
}

__global__ void __launch_bounds__(256, 2) k_gemm_tma(int layer, const float* __restrict__ bias)
{
    extern __shared__ char smem[];
    uint32_t sb = smem_u32(smem);
    int tid = threadIdx.x, warp = tid >> 5, lane = tid & 31;
    int mc = blockIdx.x, jblk = blockIdx.y;

    if (tid == 0) {
#pragma unroll
        for (int s = 0; s < 4; s++) MB_INIT(sb + MBOFF + s * 8);
    }
    __syncthreads();

    if (jblk < 2) gemm_body<7>(sb, layer, jblk, mc, bias, tid, warp, lane);
    else          gemm_body<5>(sb, layer, jblk, mc, bias, tid, warp, lane);
}

// ---------------- aggregation + BN + relu -> A fragments (layers 0..3) ----------------
// BN params loaded in the EPILOGUE (not held across the gather loop) to cut live
// registers -> 3 CTAs/SM.
__global__ void __launch_bounds__(256, 3) k_aggr_frag(int layer,
                                                      const float* __restrict__ rm,
                                                      const float* __restrict__ rv,
                                                      const float* __restrict__ gg,
                                                      const float* __restrict__ bb)
{
    __shared__ float hs[16][HSW];
    int tid = threadIdx.x, warp = tid >> 5, lane = tid & 31;
    int base = blockIdx.x * 16;
    const float4* ve4 = (const float4*)(g_ve_all + (size_t)layer * 2 * EMB);

    float4 e0[3], e1[3];
#pragma unroll
    for (int i = 0; i < 3; i++) {
        int c = lane + 32 * i;
        if (c < EMB4) { e0[i] = __ldg(ve4 + c); e1[i] = __ldg(ve4 + EMB4 + c); }
    }
#pragma unroll
    for (int ni = 0; ni < 2; ni++) {
        int row = warp * 2 + ni;
        int gw = base + row;
        float4 acc[3];
#pragma unroll
        for (int i = 0; i < 3; i++) acc[i] = make_float4(0.f, 0.f, 0.f, 0.f);
        int beg = g_off[gw], end = g_off[gw + 1];
        for (int e = beg; e < end; e++) {
            int src = g_csr_src[e];
            float2 ea = g_csr_ea[e];
            const float4* rowp = (const float4*)(g_hW + (size_t)src * EMB);
#pragma unroll
            for (int i = 0; i < 3; i++) {
                int c = lane + 32 * i;
                if (c < EMB4) {
                    float4 x = rowp[c];
                    acc[i].x += fmaxf(fmaf(ea.y, e1[i].x, fmaf(ea.x, e0[i].x, x.x)), 0.f);
                    acc[i].y += fmaxf(fmaf(ea.y, e1[i].y, fmaf(ea.x, e0[i].y, x.y)), 0.f);
                    acc[i].z += fmaxf(fmaf(ea.y, e1[i].z, fmaf(ea.x, e0[i].z, x.z)), 0.f);
                    acc[i].w += fmaxf(fmaf(ea.y, e1[i].w, fmaf(ea.x, e0[i].w, x.w)), 0.f);
                }
            }
        }
        // epilogue: BN params loaded here (L1-hot, not live during gather)
#pragma unroll
        for (int i = 0; i < 3; i++) {
            int c = lane + 32 * i;
            if (c < EMB4) {
                float4 m = __ldg((const float4*)rm + c);
                float4 v = __ldg((const float4*)rv + c);
                float4 g4 = __ldg((const float4*)gg + c);
                float4 b4 = __ldg((const float4*)bb + c);
                float4 y;
                y.x = fmaxf((acc[i].x - m.x) * rsqrtf(v.x + 1e-5f) * g4.x + b4.x, 0.f);
                y.y = fmaxf((acc[i].y - m.y) * rsqrtf(v.y + 1e-5f) * g4.y + b4.y, 0.f);
                y.z = fmaxf((acc[i].z - m.z) * rsqrtf(v.z + 1e-5f) * g4.z + b4.z, 0.f);
                y.w = fmaxf((acc[i].w - m.w) * rsqrtf(v.w + 1e-5f) * g4.w + b4.w, 0.f);
                *(float4*)&hs[row][4 * c] = y;
            }
        }
        hs[row][300 + lane] = 0.f;
    }
    __syncthreads();
    write_frags_from_smem(hs, blockIdx.x, warp, lane);
}

// ---------------- last layer aggregation + BN (no relu) -> g_h linear ----------------
__global__ void __launch_bounds__(256, 4) k_aggr_last(int layer,
                                                      const float* __restrict__ rm,
                                                      const float* __restrict__ rv,
                                                      const float* __restrict__ gg,
                                                      const float* __restrict__ bb)
{
    int gw = (blockIdx.x * blockDim.x + threadIdx.x) >> 5;
    if (gw >= NNODES) return;
    int lane = threadIdx.x & 31;
    const float4* ve4 = (const float4*)(g_ve_all + (size_t)layer * 2 * EMB);

    float4 acc[3], e0[3], e1[3];
#pragma unroll
    for (int i = 0; i < 3; i++) {
        acc[i] = make_float4(0.f, 0.f, 0.f, 0.f);
        int c = lane + 32 * i;
        if (c < EMB4) { e0[i] = __ldg(ve4 + c); e1[i] = __ldg(ve4 + EMB4 + c); }
    }
    int beg = g_off[gw], end = g_off[gw + 1];
    for (int e = beg; e < end; e++) {
        int src = g_csr_src[e];
        float2 ea = g_csr_ea[e];
        const float4* row = (const float4*)(g_hW + (size_t)src * EMB);
#pragma unroll
        for (int i = 0; i < 3; i++) {
            int c = lane + 32 * i;
            if (c < EMB4) {
                float4 x = row[c];
                acc[i].x += fmaxf(fmaf(ea.y, e1[i].x, fmaf(ea.x, e0[i].x, x.x)), 0.f);
                acc[i].y += fmaxf(fmaf(ea.y, e1[i].y, fmaf(ea.x, e0[i].y, x.y)), 0.f);
                acc[i].z += fmaxf(fmaf(ea.y, e1[i].z, fmaf(ea.x, e0[i].z, x.z)), 0.f);
                acc[i].w += fmaxf(fmaf(ea.y, e1[i].w, fmaf(ea.x, e0[i].w, x.w)), 0.f);
            }
        }
    }
#pragma unroll
    for (int i = 0; i < 3; i++) {
        int c = lane + 32 * i;
        if (c < EMB4) {
            float4 m = __ldg((const float4*)rm + c);
            float4 v = __ldg((const float4*)rv + c);
            float4 g4 = __ldg((const float4*)gg + c);
            float4 b4 = __ldg((const float4*)bb + c);
            float4 y;
            y.x = (acc[i].x - m.x) * rsqrtf(v.x + 1e-5f) * g4.x + b4.x;
            y.y = (acc[i].y - m.y) * rsqrtf(v.y + 1e-5f) * g4.y + b4.y;
            y.z = (acc[i].z - m.z) * rsqrtf(v.z + 1e-5f) * g4.z + b4.z;
            y.w = (acc[i].w - m.w) * rsqrtf(v.w + 1e-5f) * g4.w + b4.w;
            ((float4*)(g_h + (size_t)gw * EMB))[c] = y;
        }
    }
}

// ---------------- readout ----------------
__global__ void k_q()
{
    __shared__ float mfs[4][EMB];
    int b0 = blockIdx.x * 4, tid = threadIdx.x;
    for (int i = tid; i < 4 * EMB; i += 256)
        mfs[i / EMB][i % EMB] = g_mf[(size_t)(b0 + i / EMB) * EMB + i % EMB];
    __syncthreads();
    float acc[4] = {0.f, 0.f, 0.f, 0.f};
    for (int j = 0; j < EMB; j++) {
        float w = g_wqt[(size_t)j * DK + tid];
#pragma unroll
        for (int g = 0; g < 4; g++) acc[g] = fmaf(mfs[g][j], w, acc[g]);
    }
#pragma unroll
    for (int g = 0; g < 4; g++) g_Q[(size_t)(b0 + g) * DK + tid] = acc[g];
}

__global__ void k_qk(const float* __restrict__ wk)
{
    __shared__ float Qs[4][DK];
    int b0 = blockIdx.x * 4, tid = threadIdx.x;
    for (int i = tid; i < 4 * DK; i += 320)
        Qs[i / DK][i % DK] = g_Q[(size_t)(b0 + i / DK) * DK + i % DK];
    __syncthreads();
    if (tid < EMB) {
        float acc[4] = {0.f, 0.f, 0.f, 0.f};
        for (int d = 0; d < DK; d++) {
            float w = __ldg(wk + (size_t)d * EMB + tid);
#pragma unroll
            for (int g = 0; g < 4; g++) acc[g] = fmaf(Qs[g][d], w, acc[g]);
        }
#pragma unroll
        for (int g = 0; g < 4; g++) g_qk[(size_t)(b0 + g) * EMB + tid] = acc[g];
    }
}

__global__ void k_attn()
{
    __shared__ float qks[EMB];
    __shared__ float sc[NPER];
    __shared__ float p[NPER];
    int b = blockIdx.x, tid = threadIdx.x;
    for (int i = tid; i < EMB; i += 256) qks[i] = g_qk[(size_t)b * EMB + i];
    __syncthreads();
    int warp = tid >> 5, lane = tid & 31;
    const float* hb = g_h + (size_t)b * NPER * EMB;
    for (int k = warp; k < NPER; k += 8) {
        float s = 0.f;
        for (int i = lane; i < EMB; i += 32) s = fmaf(qks[i], hb[(size_t)k * EMB + i], s);
#pragma unroll
        for (int off = 16; off; off >>= 1) s += __shfl_xor_sync(0xffffffffu, s, off);
        if (lane == 0) sc[k] = s * (1.0f / 16.0f);
    }
    __syncthreads();
    if (tid == 0) {
        float mx = -1e30f;
        for (int k = 0; k < NPER; k++) mx = fmaxf(mx, sc[k]);
        float ssum = 0.f;
        for (int k = 0; k < NPER; k++) { float e = expf(sc[k] - mx); p[k] = e; ssum += e; }
        float inv = 1.f / ssum;
        for (int k = 0; k < NPER; k++) p[k] *= inv;
    }
    __syncthreads();
    for (int j = tid; j < EMB; j += 256) {
        float ws = 0.f, mn = 0.f;
        for (int k = 0; k < NPER; k++) {
            float v = hb[(size_t)k * EMB + j];
            ws = fmaf(p[k], v, ws); mn += v;
        }
        g_wsum[(size_t)b * EMB + j] = ws;
        g_mean[(size_t)b * EMB + j] = mn * (1.0f / NPER);
    }
}

__global__ void k_final(const float* __restrict__ ml_b, const float* __restrict__ lg_b,
                        const float* __restrict__ ph1_b, const float* __restrict__ ph2_w,
                        const float* __restrict__ ph2_b, float* __restrict__ out)
{
    __shared__ float ws[4][EMB], mfs[4][EMB], mns[4][EMB];
    __shared__ float feat[4][DK];
    __shared__ float red[256];
    int b0 = blockIdx.x * 4, tid = threadIdx.x;
    for (int i = tid; i < 4 * EMB; i += 256) {
        int g = i / EMB, j = i % EMB;
        ws[g][j]  = g_wsum[(size_t)(b0 + g) * EMB + j];
        mfs[g][j] = g_mf[(size_t)(b0 + g) * EMB + j];
        mns[g][j] = g_mean[(size_t)(b0 + g) * EMB + j];
    }
    __syncthreads();
    int d = tid;
    float a[4], m2[4], lg[4];
    float mb = __ldg(ml_b + d), lb = __ldg(lg_b + d);
#pragma unroll
    for (int g = 0; g < 4; g++) { a[g] = 0.f; m2[g] = mb; lg[g] = lb; }
    for (int k = 0; k < EMB; k++) {
        float wv_ = g_wvt[(size_t)k * DK + d];
        float ml_ = g_mlt[(size_t)k * DK + d];
        float lg_ = g_lgt[(size_t)k * DK + d];
#pragma unroll
        for (int g = 0; g < 4; g++) {
            a[g]  = fmaf(wv_, ws[g][k],  a[g]);
            m2[g] = fmaf(ml_, mfs[g][k], m2[g]);
            lg[g] = fmaf(lg_, mns[g][k], lg[g]);
        }
    }
#pragma unroll
    for (int g = 0; g < 4; g++)
        feat[g][d] = fmaxf(a[g], 0.f) + fmaxf(m2[g], 0.f) + fmaxf(lg[g], 0.f);
    __syncthreads();
    float part[4] = {0.f, 0.f, 0.f, 0.f};
#pragma unroll
    for (int rep = 0; rep < 2; rep++) {
        int o = tid + rep * 256;
        float t[4];
        float pb = __ldg(ph1_b + o);
#pragma unroll
        for (int g = 0; g < 4; g++) t[g] = pb;
        for (int k = 0; k < DK; k++) {
            float w = g_ph1t[(size_t)k * 512 + o];
#pragma unroll
            for (int g = 0; g < 4; g++) t[g] = fmaf(w, feat[g][k], t[g]);
        }
        float p2 = __ldg(ph2_w + o);
#pragma unroll
        for (int g = 0; g < 4; g++) {
            float x = t[g];
            float sp = (x > 20.f) ? x : log1pf(expf(x));
            part[g] = fmaf(sp, p2, part[g]);
        }
    }
    for (int g = 0; g < 4; g++) {
        red[tid] = part[g];
        __syncthreads();
        for (int s = 128; s; s >>= 1) {
            if (tid < s) red[tid] += red[tid + s];
            __syncthreads();
        }
        if (tid == 0) out[b0 + g] = red[0] + __ldg(ph2_b);
        __syncthreads();
    }
}

// ---------------- launch ----------------
extern "C" void kernel_launch(void* const* d_in, const int* in_sizes, int n_in,
                              void* d_out, int out_size)
{
    const int*   x_type     = (const int*)d_in[0];
    const float* x_feat     = (const float*)d_in[1];
    const int*   edge_index = (const int*)d_in[2];
    const float* edge_attr  = (const float*)d_in[3];
    const int*   metal_type = (const int*)d_in[4];
    const float* metal_feat = (const float*)d_in[5];
    const float* x_emb      = (const float*)d_in[6];
    const float* x_weight   = (const float*)d_in[7];
    const float* ew1        = (const float*)d_in[8];
    const float* mlp_w      = (const float*)d_in[9];
    const float* mlp_b      = (const float*)d_in[10];
    const float* bn_g       = (const float*)d_in[11];
    const float* bn_b       = (const float*)d_in[12];
    const float* bn_rm      = (const float*)d_in[13];
    const float* bn_rv      = (const float*)d_in[14];
    const float* me1_w      = (const float*)d_in[15];
    const float* me1_b      = (const float*)d_in[16];
    const float* me2        = (const float*)d_in[17];
    const float* wq         = (const float*)d_in[18];
    const float* wk         = (const float*)d_in[19];
    const float* wv         = (const float*)d_in[20];
    const float* ml_w       = (const float*)d_in[21];
    const float* ml_b       = (const float*)d_in[22];
    const float* lg_w       = (const float*)d_in[23];
    const float* lg_b       = (const float*)d_in[24];
    const float* ph1_w      = (const float*)d_in[25];
    const float* ph1_b      = (const float*)d_in[26];
    const float* ph2_w      = (const float*)d_in[27];
    const float* ph2_b      = (const float*)d_in[28];
    float* out = (float*)d_out;

    cudaFuncSetAttribute(k_gemm_tma, cudaFuncAttributeMaxDynamicSharedMemorySize, GEMM_SMEM);

    k_init_frag<<<NNODES / 16, 256>>>(x_type, x_feat, x_emb, x_weight);
    k_wsplit_frag<<<(NLAYERS * NJB * NKT * NTL * 32 + 255) / 256, 256>>>(mlp_w);
    k_prep<<<(PR_TOTAL + 255) / 256, 256>>>(metal_type, metal_feat, me1_w, me1_b, me2,
                                            ew1, mlp_w, wq, wv, ml_w, lg_w, ph1_w);
    k_deg_count<<<(NEDGES + 255) / 256, 256>>>(edge_index);
    k_scan<<<1, 1024>>>();
    k_fill<<<(TOTE + 255) / 256, 256>>>(edge_index, edge_attr);

    for (int l = 0; l < NLAYERS; l++) {
        k_gemm_tma<<<dim3(NMCH, NJB), 256, GEMM_SMEM>>>(l, mlp_b + (size_t)l * EMB);
        if (l < NLAYERS - 1)
            k_aggr_frag<<<NNODES / 16, 256>>>(
                l, bn_rm + (size_t)l * EMB, bn_rv + (size_t)l * EMB,
                bn_g + (size_t)l * EMB, bn_b + (size_t)l * EMB);
        else
            k_aggr_last<<<(NNODES * 32 + 255) / 256, 256>>>(
                l, bn_rm + (size_t)l * EMB, bn_rv + (size_t)l * EMB,
                bn_g + (size_t)l * EMB, bn_b + (size_t)l * EMB);
    }

    k_q<<<BGR / 4, 256>>>();
    k_qk<<<BGR / 4, 320>>>(wk);
    k_attn<<<BGR, 256>>>();
    k_final<<<BGR / 4, 256>>>(ml_b, lg_b, ph1_b, ph2_w, ph2_b, out);
}